// round 1
// baseline (speedup 1.0000x reference)
#include <cuda_runtime.h>
#include <cuda_bf16.h>

typedef long long ll;

// Problem dims
#define NB 256
#define NS 32
#define ND 512
#define NHW 196

// ---------------- scratch (single __device__ array, no allocation) -------
// offsets in floats
#define BDSZ   (NB*ND)                   // 131072
#define OFF_Q     ((ll)0)
#define OFF_PA    ((ll)BDSZ*1)
#define OFF_CQ    ((ll)BDSZ*2)
#define OFF_PM    ((ll)BDSZ*3)
#define OFF_PMC   ((ll)BDSZ*4)
#define OFF_V     ((ll)BDSZ*5)
#define OFF_U     ((ll)BDSZ*6)
#define OFF_READ  ((ll)BDSZ*7)
#define OFF_C     ((ll)BDSZ*8)                   // NB floats
#define OFF_KBD   (OFF_C + 256)                  // ND floats
#define OFF_WKW   (OFF_KBD + 512)                // ND*ND
#define OFF_LOGIT (OFF_WKW + (ll)ND*ND)          // NB*NHW
#define OFF_AR    (OFF_LOGIT + (ll)NB*NHW)
#define OFF_SPK   (OFF_AR + (ll)NB*NHW)          // NB*NHW*ND
#define OFF_H     (OFF_SPK + (ll)NB*NHW*ND)
#define TOTAL_F   (OFF_H + (ll)NB*NHW*ND)        // 52,792,064 floats ~= 211MB

__device__ float g_s[52792064];

enum { ACT_NONE = 0, ACT_TANH = 1, ACT_RELU = 2 };

// ---------------- generic strided/batched fp32 GEMM ----------------------
// C[b][m,n] = act( (sum_k A[m,k]*B[k,n]) + bias[n] ) with optional per-n
// column scale (applied after bias) and beta accumulate (before act).
// A element (m,k) at A + b*aB + m*aM + k*aK   (strides in elements)
// B element (k,n) at B + b*bB + k*bK + n*bN
// C row-major, leading dim N.
__global__ __launch_bounds__(256)
void gemm_k(const float* __restrict__ A, ll aB, ll aM, ll aK,
            const float* __restrict__ Bm, ll bB, ll bK, ll bN,
            float* __restrict__ C, ll cB,
            const float* __restrict__ bias, ll biasB,
            const float* __restrict__ cs, ll csB,
            int M, int N, int K, int beta, int act)
{
    const int bz = blockIdx.z;
    A  += (ll)bz * aB;
    Bm += (ll)bz * bB;
    C  += (ll)bz * cB;
    if (bias) bias += (ll)bz * biasB;
    if (cs)   cs   += (ll)bz * csB;

    const int m0 = blockIdx.y * 128;
    const int n0 = blockIdx.x * 128;

    __shared__ float As[8][132];   // padded to 132 for conflict-free writes
    __shared__ float Bs[8][128];

    float acc[8][8];
#pragma unroll
    for (int i = 0; i < 8; i++)
#pragma unroll
        for (int j = 0; j < 8; j++) acc[i][j] = 0.f;

    const int tid = threadIdx.x;
    const int tx = tid & 15;
    const int ty = tid >> 4;
    const bool kContigA = (aK == 1);   // pick coalesced load mapping for A

    for (int k0 = 0; k0 < K; k0 += 8) {
#pragma unroll
        for (int r = 0; r < 4; r++) {
            int i = tid + r * 256;
            int mm, kk;
            if (kContigA) { kk = i & 7;   mm = i >> 3; }
            else          { mm = i & 127; kk = i >> 7; }
            int gm = m0 + mm, gk = k0 + kk;
            float va = 0.f;
            if (gm < M && gk < K) va = A[(ll)gm * aM + (ll)gk * aK];
            As[kk][mm] = va;

            int nn = i & 127, kb = i >> 7;
            int gn = n0 + nn, gkb = k0 + kb;
            float vb = 0.f;
            if (gn < N && gkb < K) vb = Bm[(ll)gkb * bK + (ll)gn * bN];
            Bs[kb][nn] = vb;
        }
        __syncthreads();
#pragma unroll
        for (int kk = 0; kk < 8; kk++) {
            float4 a0 = *(const float4*)&As[kk][ty * 4];
            float4 a1 = *(const float4*)&As[kk][ty * 4 + 64];
            float4 b0 = *(const float4*)&Bs[kk][tx * 4];
            float4 b1 = *(const float4*)&Bs[kk][tx * 4 + 64];
            float a[8] = {a0.x, a0.y, a0.z, a0.w, a1.x, a1.y, a1.z, a1.w};
            float b[8] = {b0.x, b0.y, b0.z, b0.w, b1.x, b1.y, b1.z, b1.w};
#pragma unroll
            for (int i = 0; i < 8; i++)
#pragma unroll
                for (int j = 0; j < 8; j++)
                    acc[i][j] = fmaf(a[i], b[j], acc[i][j]);
        }
        __syncthreads();
    }

#pragma unroll
    for (int ih = 0; ih < 2; ih++)
#pragma unroll
    for (int i = 0; i < 4; i++) {
        int gm = m0 + ih * 64 + ty * 4 + i;
        if (gm >= M) continue;
#pragma unroll
        for (int jh = 0; jh < 2; jh++)
#pragma unroll
        for (int j = 0; j < 4; j++) {
            int gn = n0 + jh * 64 + tx * 4 + j;
            if (gn >= N) continue;
            float v = acc[ih * 4 + i][jh * 4 + j];
            if (bias) v += bias[gn];
            if (cs)   v *= cs[gn];
            if (beta) v += C[(ll)gm * N + gn];
            if (act == ACT_TANH)      v = tanhf(v);
            else if (act == ACT_RELU) v = fmaxf(v, 0.f);
            C[(ll)gm * N + gn] = v;
        }
    }
}

// --------- word attention: logit_c softmax over S, control = sum --------
__global__ __launch_bounds__(256)
void attnc_kernel(const float* __restrict__ words,
                  const float* __restrict__ cq,
                  const float* __restrict__ wac,
                  const float* __restrict__ bac,
                  float* __restrict__ control /* -> d_out[0:B*D] */)
{
    const int b = blockIdx.x;
    const int tid = threadIdx.x;
    const int warp = tid >> 5, lane = tid & 31;
    __shared__ float cw[ND];
    __shared__ float sa[NS];

    for (int d = tid; d < ND; d += 256)
        cw[d] = cq[(ll)b * ND + d] * wac[d];
    __syncthreads();

    // 8 warps x 4 s each
#pragma unroll
    for (int r = 0; r < 4; r++) {
        int s = warp * 4 + r;
        const float* wp = words + ((ll)b * NS + s) * ND;
        float acc = 0.f;
        for (int d = lane; d < ND; d += 32) acc += cw[d] * wp[d];
#pragma unroll
        for (int o = 16; o; o >>= 1) acc += __shfl_xor_sync(0xffffffffu, acc, o);
        if (lane == 0) sa[s] = acc + bac[0];
    }
    __syncthreads();

    if (warp == 0) {
        float v = sa[lane];
        float mx = v;
#pragma unroll
        for (int o = 16; o; o >>= 1) mx = fmaxf(mx, __shfl_xor_sync(0xffffffffu, mx, o));
        float e = expf(v - mx);
        float sm = e;
#pragma unroll
        for (int o = 16; o; o >>= 1) sm += __shfl_xor_sync(0xffffffffu, sm, o);
        sa[lane] = e / sm;
    }
    __syncthreads();

    for (int d = tid; d < ND; d += 256) {
        float acc = 0.f;
#pragma unroll 8
        for (int s = 0; s < NS; s++)
            acc += sa[s] * words[((ll)b * NS + s) * ND + d];
        control[(ll)b * ND + d] = acc;
    }
}

// --------- v = control*war ; c_b = bc2.v + bar --------------------------
__global__ __launch_bounds__(256)
void vc_kernel(const float* __restrict__ control, const float* __restrict__ war,
               const float* __restrict__ bc2, const float* __restrict__ bar,
               float* __restrict__ v, float* __restrict__ c)
{
    const int b = blockIdx.x, tid = threadIdx.x;
    __shared__ float s[256];
    float p = 0.f;
    for (int d = tid; d < ND; d += 256) {
        float vv = control[(ll)b * ND + d] * war[d];
        v[(ll)b * ND + d] = vv;
        p += bc2[d] * vv;
    }
    s[tid] = p; __syncthreads();
    for (int o = 128; o; o >>= 1) { if (tid < o) s[tid] += s[tid + o]; __syncthreads(); }
    if (tid == 0) c[b] = s[0] + bar[0];
}

// --------- kbd[d] = sum_e bk[e]*Wc1[D+e][d] ------------------------------
__global__ void kbd_kernel(const float* __restrict__ Wc1,
                           const float* __restrict__ bk, float* __restrict__ kbd)
{
    int d = blockIdx.x * 256 + threadIdx.x;
    float acc = 0.f;
    for (int e = 0; e < ND; e++) acc += bk[e] * Wc1[(ll)(ND + e) * ND + d];
    kbd[d] = acc;
}

__global__ void addvec_kernel(float* __restrict__ pmc, const float* __restrict__ kbd)
{
    int i = blockIdx.x * 256 + threadIdx.x;
    pmc[i] += kbd[i & (ND - 1)];
}

// --------- logit_r[b,n] = relu_h[b,n,:].u[b] + c[b] ----------------------
__global__ __launch_bounds__(256)
void logitr_kernel(const float* __restrict__ h, const float* __restrict__ u,
                   const float* __restrict__ c, float* __restrict__ logit)
{
    int gi = blockIdx.x * 8 + (threadIdx.x >> 5);
    int lane = threadIdx.x & 31;
    if (gi >= NB * NHW) return;
    int b = gi / NHW;
    const float* hp = h + (ll)gi * ND;
    const float* up = u + (ll)b * ND;
    float acc = 0.f;
    for (int d = lane; d < ND; d += 32) acc += hp[d] * up[d];
#pragma unroll
    for (int o = 16; o; o >>= 1) acc += __shfl_xor_sync(0xffffffffu, acc, o);
    if (lane == 0) logit[gi] = acc + c[b];
}

// --------- softmax over n (196) per b ------------------------------------
__global__ __launch_bounds__(256)
void softmaxn_kernel(const float* __restrict__ logit, float* __restrict__ ar)
{
    const int b = blockIdx.x, tid = threadIdx.x;
    __shared__ float s[256];
    float v = (tid < NHW) ? logit[(ll)b * NHW + tid] : -1e30f;
    s[tid] = v; __syncthreads();
    for (int o = 128; o; o >>= 1) { if (tid < o) s[tid] = fmaxf(s[tid], s[tid + o]); __syncthreads(); }
    float mx = s[0]; __syncthreads();
    float e = (tid < NHW) ? expf(v - mx) : 0.f;
    s[tid] = e; __syncthreads();
    for (int o = 128; o; o >>= 1) { if (tid < o) s[tid] += s[tid + o]; __syncthreads(); }
    float sum = s[0];
    if (tid < NHW) ar[(ll)b * NHW + tid] = e / sum;
}

// --------- read[b,d] = sum_n know[b,d,n]*a_r[b,n] -------------------------
__global__ __launch_bounds__(256)
void read_kernel(const float* __restrict__ know, const float* __restrict__ ar,
                 float* __restrict__ rd)
{
    const int b = blockIdx.x, tid = threadIdx.x;
    const int warp = tid >> 5, lane = tid & 31;
    __shared__ float s[NHW];
    if (tid < NHW) s[tid] = ar[(ll)b * NHW + tid];
    __syncthreads();
    for (int d = warp; d < ND; d += 8) {
        const float* kp = know + ((ll)b * ND + d) * NHW;
        float acc = 0.f;
        for (int n = lane; n < NHW; n += 32) acc += kp[n] * s[n];
#pragma unroll
        for (int o = 16; o; o >>= 1) acc += __shfl_xor_sync(0xffffffffu, acc, o);
        if (lane == 0) rd[(ll)b * ND + d] = acc;
    }
}

// -------------------------------------------------------------------------
static void launch_gemm(const float* A, ll aB, ll aM, ll aK,
                        const float* Bm, ll bB, ll bK, ll bN,
                        float* C, ll cB,
                        const float* bias, ll biasB,
                        const float* cs, ll csB,
                        int M, int N, int K, int beta, int act, int batch)
{
    dim3 grid((N + 127) / 128, (M + 127) / 128, batch);
    gemm_k<<<grid, 256>>>(A, aB, aM, aK, Bm, bB, bK, bN, C, cB,
                          bias, biasB, cs, csB, M, N, K, beta, act);
}

extern "C" void kernel_launch(void* const* d_in, const int* in_sizes, int n_in,
                              void* d_out, int out_size)
{
    const float* words    = (const float*)d_in[0];
    const float* question = (const float*)d_in[1];
    const float* know     = (const float*)d_in[2];
    const float* control0 = (const float*)d_in[3];
    const float* memory0  = (const float*)d_in[4];
    const float* Wsc  = (const float*)d_in[5];
    const float* bsc  = (const float*)d_in[6];
    const float* Wp   = (const float*)d_in[7];
    const float* bp   = (const float*)d_in[8];
    const float* Wcq  = (const float*)d_in[9];
    const float* bcq  = (const float*)d_in[10];
    const float* wac  = (const float*)d_in[11];
    const float* bac  = (const float*)d_in[12];
    const float* Wm   = (const float*)d_in[13];
    const float* bm   = (const float*)d_in[14];
    const float* Wk   = (const float*)d_in[15];
    const float* bk   = (const float*)d_in[16];
    const float* Wc1  = (const float*)d_in[17];
    const float* bc1  = (const float*)d_in[18];
    const float* Wc2  = (const float*)d_in[19];
    const float* bc2  = (const float*)d_in[20];
    const float* war  = (const float*)d_in[21];
    const float* bar  = (const float*)d_in[22];
    // d_in[23..26] (Wwc, bwc, waw, baw) are mathematically dead: softmax over
    // a length-1 axis makes a_w == 1, so attn_mem == memory0.
    const float* Wwcat = (const float*)d_in[27];
    const float* bwcat = (const float*)d_in[28];

    float* S = nullptr;
    cudaGetSymbolAddress((void**)&S, g_s);

    float* outC = (float*)d_out;                 // control  (B, D)
    float* outM = (float*)d_out + (ll)NB * ND;   // next_mem (B, D)

    const int D = ND, B = NB;

    // q = tanh(question @ Wsc + bsc)
    launch_gemm(question, 0, 2 * D, 1, Wsc, 0, D, 1, S + OFF_Q, 0,
                bsc, 0, nullptr, 0, B, D, 2 * D, 0, ACT_TANH, 1);
    // pa = q @ Wp + bp
    launch_gemm(S + OFF_Q, 0, D, 1, Wp, 0, D, 1, S + OFF_PA, 0,
                bp, 0, nullptr, 0, B, D, D, 0, ACT_NONE, 1);
    // cq = control0 @ Wcq[:D] + bcq  ;  cq += pa @ Wcq[D:]
    launch_gemm(control0, 0, D, 1, Wcq, 0, D, 1, S + OFF_CQ, 0,
                bcq, 0, nullptr, 0, B, D, D, 0, ACT_NONE, 1);
    launch_gemm(S + OFF_PA, 0, D, 1, Wcq + (ll)D * D, 0, D, 1, S + OFF_CQ, 0,
                nullptr, 0, nullptr, 0, B, D, D, 1, ACT_NONE, 1);
    // word attention -> control (directly into output)
    attnc_kernel<<<B, 256>>>(words, S + OFF_CQ, wac, bac, outC);

    // pm = memory0 @ Wm + bm
    launch_gemm(memory0, 0, D, 1, Wm, 0, D, 1, S + OFF_PM, 0,
                bm, 0, nullptr, 0, B, D, D, 0, ACT_NONE, 1);
    // WkW1b = Wk @ Wc1[D:2D]
    launch_gemm(Wk, 0, D, 1, Wc1 + (ll)D * D, 0, D, 1, S + OFF_WKW, 0,
                nullptr, 0, nullptr, 0, D, D, D, 0, ACT_NONE, 1);
    // pmc = pm @ Wc1[2D:3D] + bc1 ; pmc += bk @ Wc1[D:2D]
    launch_gemm(S + OFF_PM, 0, D, 1, Wc1 + (ll)2 * D * D, 0, D, 1, S + OFF_PMC, 0,
                bc1, 0, nullptr, 0, B, D, D, 0, ACT_NONE, 1);
    kbd_kernel<<<2, 256>>>(Wc1, bk, S + OFF_KBD);
    addvec_kernel<<<(B * D) / 256, 256>>>(S + OFF_PMC, S + OFF_KBD);

    // v = control*war ; c_b = bc2.v + bar ; u = v @ Wc2^T
    vc_kernel<<<B, 256>>>(outC, war, bc2, bar, S + OFF_V, S + OFF_C);
    launch_gemm(S + OFF_V, 0, D, 1, Wc2, 0, 1, D, S + OFF_U, 0,
                nullptr, 0, nullptr, 0, B, D, D, 0, ACT_NONE, 1);

    // HEAVY: spk[b,n,e] = pm[b,e] * (sum_d know[b,d,n]*Wk[d,e] + bk[e])
    launch_gemm(know, (ll)D * NHW, 1, NHW, Wk, 0, D, 1,
                S + OFF_SPK, (ll)NHW * D,
                bk, 0, S + OFF_PM, D,
                NHW, D, D, 0, ACT_NONE, B);
    // HEAVY: h = spk @ W1a + pmc(broadcast bias)
    launch_gemm(S + OFF_SPK, (ll)NHW * D, D, 1, Wc1, 0, D, 1,
                S + OFF_H, (ll)NHW * D,
                S + OFF_PMC, D, nullptr, 0,
                NHW, D, D, 0, ACT_NONE, B);
    // HEAVY: h += know^T @ WkW1b ; relu
    launch_gemm(know, (ll)D * NHW, 1, NHW, S + OFF_WKW, 0, D, 1,
                S + OFF_H, (ll)NHW * D,
                nullptr, 0, nullptr, 0,
                NHW, D, D, 1, ACT_RELU, B);

    // logit_r, softmax over n, read
    logitr_kernel<<<(B * NHW + 7) / 8, 256>>>(S + OFF_H, S + OFF_U, S + OFF_C, S + OFF_LOGIT);
    softmaxn_kernel<<<B, 256>>>(S + OFF_LOGIT, S + OFF_AR);
    read_kernel<<<B, 256>>>(know, S + OFF_AR, S + OFF_READ);

    // next_mem = read @ Wwcat[:D] + memory0 @ Wwcat[D:2D] + memory0 @ Wwcat[2D:3D] + bwcat
    launch_gemm(S + OFF_READ, 0, D, 1, Wwcat, 0, D, 1, outM, 0,
                bwcat, 0, nullptr, 0, B, D, D, 0, ACT_NONE, 1);
    launch_gemm(memory0, 0, D, 1, Wwcat + (ll)D * D, 0, D, 1, outM, 0,
                nullptr, 0, nullptr, 0, B, D, D, 1, ACT_NONE, 1);
    launch_gemm(memory0, 0, D, 1, Wwcat + (ll)2 * D * D, 0, D, 1, outM, 0,
                nullptr, 0, nullptr, 0, B, D, D, 1, ACT_NONE, 1);
}

// round 2
// speedup vs baseline: 2.1087x; 2.1087x over previous
#include <cuda_runtime.h>
#include <cuda_bf16.h>

typedef long long ll;

#define NB 256
#define NS 32
#define ND 512
#define NHW 196
#define NM (NB*NHW)   // 50176 global rows for heavy GEMMs

// ---------------- scratch offsets (floats) --------------------------------
#define BD (NB*ND)
#define OFF_Q     ((ll)0)
#define OFF_PA    ((ll)131072)
#define OFF_CQ    ((ll)262144)
#define OFF_PM    ((ll)393216)
#define OFF_PMC   ((ll)524288)
#define OFF_V     ((ll)655360)
#define OFF_U     ((ll)786432)
#define OFF_READ  ((ll)917504)
#define OFF_C     ((ll)1048576)
#define OFF_KBD   ((ll)1048832)
#define OFF_WKW   ((ll)1049344)
#define OFF_WSUM  ((ll)1311488)
#define OFF_LOGIT ((ll)1573632)
#define OFF_AR    ((ll)1623808)
#define OFF_KNOWT ((ll)1673984)
#define OFF_SPK   ((ll)27364096)

__device__ float g_s[53054208];

enum { ACT_NONE = 0, ACT_TANH = 1, ACT_RELU = 2 };

__device__ __forceinline__ float2 u2f2(unsigned long long v) {
    float2 r;
    r.x = __uint_as_float((unsigned)v);
    r.y = __uint_as_float((unsigned)(v >> 32));
    return r;
}

// ---------------- transpose know[b,d,n] -> knowT[b,n,d] -------------------
__global__ __launch_bounds__(256)
void transpose_k(const float* __restrict__ know, float* __restrict__ knowT)
{
    __shared__ float t[32][33];
    const int b = blockIdx.z;
    const int n0 = blockIdx.x * 32, d0 = blockIdx.y * 32;
    const int tx = threadIdx.x, ty = threadIdx.y;
#pragma unroll
    for (int r = 0; r < 32; r += 8) {
        int d = d0 + ty + r, n = n0 + tx;
        float v = 0.f;
        if (n < NHW) v = know[((ll)b * ND + d) * NHW + n];
        t[ty + r][tx] = v;
    }
    __syncthreads();
#pragma unroll
    for (int r = 0; r < 32; r += 8) {
        int n = n0 + ty + r, d = d0 + tx;
        if (n < NHW) knowT[((ll)b * NHW + n) * ND + d] = t[tx][ty + r];
    }
}

// ---------------- heavy GEMM (M=NM, N=512, K in {512,1024}) ---------------
// A rows stride 512 per pointer; k<512 -> A1/B1, else A2/B2.
// MODE 0: C[m,n] = (acc + bk[n]) * pm[b*512+n],  b = m/196
// MODE 1: no C store; logit[m] += sum_n relu(acc + pmc[b,n]) * u[b,n]
__device__ __forceinline__ void hload(
    const float* __restrict__ A1, const float* __restrict__ A2,
    const float* __restrict__ B1, const float* __restrict__ B2,
    int k0, int m0, int n0, int tid, float4 ra[2], float4 rb[2])
{
    const float* ab = (k0 < 512) ? (A1 + k0) : (A2 + (k0 - 512));
    const float* bb = (k0 < 512) ? (B1 + (ll)k0 * 512) : (B2 + (ll)(k0 - 512) * 512);
#pragma unroll
    for (int r = 0; r < 2; r++) {
        int li = tid + r * 256;
        int m = li >> 2, kq = li & 3;
        ra[r] = *(const float4*)(ab + (ll)(m0 + m) * 512 + kq * 4);
        int kb = li >> 5, nq = li & 31;
        rb[r] = *(const float4*)(bb + (ll)kb * 512 + n0 + nq * 4);
    }
}

__device__ __forceinline__ void hstore(
    float As[16][132], float Bs[16][128],
    const float4 ra[2], const float4 rb[2], int tid)
{
#pragma unroll
    for (int r = 0; r < 2; r++) {
        int li = tid + r * 256;
        int m = li >> 2, kq = li & 3;
        As[kq * 4 + 0][m] = ra[r].x;
        As[kq * 4 + 1][m] = ra[r].y;
        As[kq * 4 + 2][m] = ra[r].z;
        As[kq * 4 + 3][m] = ra[r].w;
        int kb = li >> 5, nq = li & 31;
        *(float4*)&Bs[kb][nq * 4] = rb[r];
    }
}

template<int MODE>
__global__ __launch_bounds__(256, 2)
void gemm_h(const float* __restrict__ A1, const float* __restrict__ A2,
            const float* __restrict__ B1, const float* __restrict__ B2,
            int ktot,
            float* __restrict__ C,
            const float* __restrict__ bk,
            const float* __restrict__ pm,
            const float* __restrict__ pmc,
            const float* __restrict__ u,
            float* __restrict__ logit)
{
    __shared__ float As[2][16][132];
    __shared__ float Bs[2][16][128];
    __shared__ float rowsum[128];

    const int tid = threadIdx.x;
    const int tx = tid & 15, ty = tid >> 4;
    const int m0 = blockIdx.y * 128;
    const int n0 = blockIdx.x * 128;

    unsigned long long acc[8][4];
#pragma unroll
    for (int i = 0; i < 8; i++)
#pragma unroll
        for (int j = 0; j < 4; j++) acc[i][j] = 0ULL;

    float4 ra[2], rb[2];
    hload(A1, A2, B1, B2, 0, m0, n0, tid, ra, rb);
    hstore(As[0], Bs[0], ra, rb, tid);
    __syncthreads();

    int buf = 0;
    for (int k0 = 0; k0 < ktot; k0 += 16) {
        const bool has = (k0 + 16) < ktot;
        if (has) hload(A1, A2, B1, B2, k0 + 16, m0, n0, tid, ra, rb);
#pragma unroll
        for (int kk = 0; kk < 16; kk++) {
            float4 a0 = *(const float4*)&As[buf][kk][ty * 4];
            float4 a1 = *(const float4*)&As[buf][kk][ty * 4 + 64];
            ulonglong2 bb0 = *(const ulonglong2*)&Bs[buf][kk][tx * 4];
            ulonglong2 bb1 = *(const ulonglong2*)&Bs[buf][kk][tx * 4 + 64];
            unsigned long long bq[4] = {bb0.x, bb0.y, bb1.x, bb1.y};
            float av[8] = {a0.x, a0.y, a0.z, a0.w, a1.x, a1.y, a1.z, a1.w};
#pragma unroll
            for (int i = 0; i < 8; i++) {
                unsigned long long ap;
                asm("mov.b64 %0, {%1, %1};" : "=l"(ap) : "f"(av[i]));
#pragma unroll
                for (int j = 0; j < 4; j++)
                    asm("fma.rn.f32x2 %0, %1, %2, %0;"
                        : "+l"(acc[i][j]) : "l"(ap), "l"(bq[j]));
            }
        }
        if (has) hstore(As[buf ^ 1], Bs[buf ^ 1], ra, rb, tid);
        __syncthreads();
        buf ^= 1;
    }

    if (MODE == 1) {
        for (int r = tid; r < 128; r += 256) rowsum[r] = 0.f;
        __syncthreads();
    }

#pragma unroll
    for (int ri = 0; ri < 8; ri++) {
        const int lrow = (ri >> 2) * 64 + ty * 4 + (ri & 3);
        const int gm = m0 + lrow;
        const int b = gm / NHW;
        if (MODE == 0) {
#pragma unroll
            for (int g = 0; g < 2; g++) {
                int gn = n0 + g * 64 + tx * 4;
                float2 p0 = u2f2(acc[ri][2 * g]);
                float2 p1 = u2f2(acc[ri][2 * g + 1]);
                const float* pmB = pm + (ll)b * 512 + gn;
                float4 v;
                v.x = (p0.x + bk[gn + 0]) * pmB[0];
                v.y = (p0.y + bk[gn + 1]) * pmB[1];
                v.z = (p1.x + bk[gn + 2]) * pmB[2];
                v.w = (p1.y + bk[gn + 3]) * pmB[3];
                *(float4*)&C[(ll)gm * 512 + gn] = v;
            }
        } else {
            float part = 0.f;
#pragma unroll
            for (int g = 0; g < 2; g++) {
                int gn = n0 + g * 64 + tx * 4;
                const float* pc = pmc + (ll)b * 512 + gn;
                const float* uu = u + (ll)b * 512 + gn;
                float2 p0 = u2f2(acc[ri][2 * g]);
                float2 p1 = u2f2(acc[ri][2 * g + 1]);
                part += fmaxf(p0.x + pc[0], 0.f) * uu[0];
                part += fmaxf(p0.y + pc[1], 0.f) * uu[1];
                part += fmaxf(p1.x + pc[2], 0.f) * uu[2];
                part += fmaxf(p1.y + pc[3], 0.f) * uu[3];
            }
            atomicAdd(&rowsum[lrow], part);
        }
    }
    if (MODE == 1) {
        __syncthreads();
        for (int r = tid; r < 128; r += 256)
            atomicAdd(&logit[m0 + r], rowsum[r]);
    }
}

// ---------------- small GEMM: 64x64 tiles, A K-contig ---------------------
// A(m,k) = (k<ksplit ? A : A2-offset)[m*aM + k]; B(k,n) at strides bK,bN.
__global__ __launch_bounds__(256)
void gemm_s(const float* __restrict__ A, const float* __restrict__ A2,
            ll aM, int ksplit,
            const float* __restrict__ B, const float* __restrict__ B2,
            ll bK, ll bN,
            float* __restrict__ C,
            const float* __restrict__ bias,
            int M, int N, int K, int beta, int act)
{
    __shared__ float As[16][68];
    __shared__ float Bs[16][64];

    const int tid = threadIdx.x;
    const int tx = tid & 15, ty = tid >> 4;
    const int m0 = blockIdx.y * 64;
    const int n0 = blockIdx.x * 64;

    float acc[4][4];
#pragma unroll
    for (int i = 0; i < 4; i++)
#pragma unroll
        for (int j = 0; j < 4; j++) acc[i][j] = 0.f;

    for (int k0 = 0; k0 < K; k0 += 16) {
#pragma unroll
        for (int r = 0; r < 4; r++) {
            int idx = tid + r * 256;
            int kk = idx & 15, mm = idx >> 4;
            int kg = k0 + kk;
            const float* Ap = (kg < ksplit) ? A : (A2 - ksplit);
            As[kk][mm] = Ap[(ll)(m0 + mm) * aM + kg];
            int nn = idx & 63, kb = idx >> 6;
            int kg2 = k0 + kb;
            const float* Bp = (kg2 < ksplit) ? B : (B2 - (ll)ksplit * bK);
            Bs[kb][nn] = Bp[(ll)kg2 * bK + (ll)(n0 + nn) * bN];
        }
        __syncthreads();
#pragma unroll
        for (int kk = 0; kk < 16; kk++) {
            float4 a = *(const float4*)&As[kk][ty * 4];
            float4 bv = *(const float4*)&Bs[kk][tx * 4];
            float av[4] = {a.x, a.y, a.z, a.w};
            float bb[4] = {bv.x, bv.y, bv.z, bv.w};
#pragma unroll
            for (int i = 0; i < 4; i++)
#pragma unroll
                for (int j = 0; j < 4; j++)
                    acc[i][j] = fmaf(av[i], bb[j], acc[i][j]);
        }
        __syncthreads();
    }

#pragma unroll
    for (int i = 0; i < 4; i++) {
        int gm = m0 + ty * 4 + i;
#pragma unroll
        for (int j = 0; j < 4; j++) {
            int gn = n0 + tx * 4 + j;
            float v = acc[i][j];
            if (bias) v += bias[gn];
            if (beta) v += C[(ll)gm * N + gn];
            if (act == ACT_TANH)      v = tanhf(v);
            else if (act == ACT_RELU) v = fmaxf(v, 0.f);
            C[(ll)gm * N + gn] = v;
        }
    }
}

// --------- word attention ------------------------------------------------
__global__ __launch_bounds__(256)
void attnc_kernel(const float* __restrict__ words,
                  const float* __restrict__ cq,
                  const float* __restrict__ wac,
                  const float* __restrict__ bac,
                  float* __restrict__ control)
{
    const int b = blockIdx.x;
    const int tid = threadIdx.x;
    const int warp = tid >> 5, lane = tid & 31;
    __shared__ float cw[ND];
    __shared__ float sa[NS];

    for (int d = tid; d < ND; d += 256)
        cw[d] = cq[(ll)b * ND + d] * wac[d];
    __syncthreads();

#pragma unroll
    for (int r = 0; r < 4; r++) {
        int s = warp * 4 + r;
        const float* wp = words + ((ll)b * NS + s) * ND;
        float acc = 0.f;
        for (int d = lane; d < ND; d += 32) acc += cw[d] * wp[d];
#pragma unroll
        for (int o = 16; o; o >>= 1) acc += __shfl_xor_sync(0xffffffffu, acc, o);
        if (lane == 0) sa[s] = acc + bac[0];
    }
    __syncthreads();

    if (warp == 0) {
        float v = sa[lane];
        float mx = v;
#pragma unroll
        for (int o = 16; o; o >>= 1) mx = fmaxf(mx, __shfl_xor_sync(0xffffffffu, mx, o));
        float e = expf(v - mx);
        float sm = e;
#pragma unroll
        for (int o = 16; o; o >>= 1) sm += __shfl_xor_sync(0xffffffffu, sm, o);
        sa[lane] = e / sm;
    }
    __syncthreads();

    for (int d = tid; d < ND; d += 256) {
        float acc = 0.f;
#pragma unroll 8
        for (int s = 0; s < NS; s++)
            acc += sa[s] * words[((ll)b * NS + s) * ND + d];
        control[(ll)b * ND + d] = acc;
    }
}

// --------- v = control*war ; c_b = bc2.v + bar ----------------------------
__global__ __launch_bounds__(256)
void vc_kernel(const float* __restrict__ control, const float* __restrict__ war,
               const float* __restrict__ bc2, const float* __restrict__ bar,
               float* __restrict__ v, float* __restrict__ c)
{
    const int b = blockIdx.x, tid = threadIdx.x;
    __shared__ float s[256];
    float p = 0.f;
    for (int d = tid; d < ND; d += 256) {
        float vv = control[(ll)b * ND + d] * war[d];
        v[(ll)b * ND + d] = vv;
        p += bc2[d] * vv;
    }
    s[tid] = p; __syncthreads();
    for (int o = 128; o; o >>= 1) { if (tid < o) s[tid] += s[tid + o]; __syncthreads(); }
    if (tid == 0) c[b] = s[0] + bar[0];
}

__global__ void kbd_kernel(const float* __restrict__ Wc1,
                           const float* __restrict__ bk, float* __restrict__ kbd)
{
    int d = blockIdx.x * 256 + threadIdx.x;
    float acc = 0.f;
    for (int e = 0; e < ND; e++) acc += bk[e] * Wc1[(ll)(ND + e) * ND + d];
    kbd[d] = acc;
}

__global__ void addvec_kernel(float* __restrict__ pmc, const float* __restrict__ kbd)
{
    int i = blockIdx.x * 256 + threadIdx.x;
    pmc[i] += kbd[i & (ND - 1)];
}

__global__ void wsum_kernel(const float* __restrict__ Wwcat, float* __restrict__ out)
{
    int i = blockIdx.x * 256 + threadIdx.x;
    out[i] = Wwcat[(ll)ND * ND + i] + Wwcat[(ll)2 * ND * ND + i];
}

__global__ void logit_init_kernel(const float* __restrict__ c, float* __restrict__ logit)
{
    int i = blockIdx.x * 256 + threadIdx.x;
    if (i < NM) logit[i] = c[i / NHW];
}

__global__ __launch_bounds__(256)
void softmaxn_kernel(const float* __restrict__ logit, float* __restrict__ ar)
{
    const int b = blockIdx.x, tid = threadIdx.x;
    __shared__ float s[256];
    float v = (tid < NHW) ? logit[(ll)b * NHW + tid] : -1e30f;
    s[tid] = v; __syncthreads();
    for (int o = 128; o; o >>= 1) { if (tid < o) s[tid] = fmaxf(s[tid], s[tid + o]); __syncthreads(); }
    float mx = s[0]; __syncthreads();
    float e = (tid < NHW) ? expf(v - mx) : 0.f;
    s[tid] = e; __syncthreads();
    for (int o = 128; o; o >>= 1) { if (tid < o) s[tid] += s[tid + o]; __syncthreads(); }
    float sum = s[0];
    if (tid < NHW) ar[(ll)b * NHW + tid] = e / sum;
}

__global__ __launch_bounds__(256)
void read_kernel(const float* __restrict__ know, const float* __restrict__ ar,
                 float* __restrict__ rd)
{
    const int b = blockIdx.x, tid = threadIdx.x;
    const int warp = tid >> 5, lane = tid & 31;
    __shared__ float s[NHW];
    if (tid < NHW) s[tid] = ar[(ll)b * NHW + tid];
    __syncthreads();
    for (int d = warp; d < ND; d += 8) {
        const float* kp = know + ((ll)b * ND + d) * NHW;
        float acc = 0.f;
        for (int n = lane; n < NHW; n += 32) acc += kp[n] * s[n];
#pragma unroll
        for (int o = 16; o; o >>= 1) acc += __shfl_xor_sync(0xffffffffu, acc, o);
        if (lane == 0) rd[(ll)b * ND + d] = acc;
    }
}

// ---------------------------------------------------------------------------
static void small_gemm(const float* A, const float* A2, ll aM, int ksplit,
                       const float* B, const float* B2, ll bK, ll bN,
                       float* C, const float* bias,
                       int M, int N, int K, int beta, int act)
{
    dim3 grid(N / 64, M / 64);
    gemm_s<<<grid, 256>>>(A, A2, aM, ksplit, B, B2, bK, bN, C, bias,
                          M, N, K, beta, act);
}

extern "C" void kernel_launch(void* const* d_in, const int* in_sizes, int n_in,
                              void* d_out, int out_size)
{
    const float* words    = (const float*)d_in[0];
    const float* question = (const float*)d_in[1];
    const float* know     = (const float*)d_in[2];
    const float* control0 = (const float*)d_in[3];
    const float* memory0  = (const float*)d_in[4];
    const float* Wsc  = (const float*)d_in[5];
    const float* bsc  = (const float*)d_in[6];
    const float* Wp   = (const float*)d_in[7];
    const float* bp   = (const float*)d_in[8];
    const float* Wcq  = (const float*)d_in[9];
    const float* bcq  = (const float*)d_in[10];
    const float* wac  = (const float*)d_in[11];
    const float* bac  = (const float*)d_in[12];
    const float* Wm   = (const float*)d_in[13];
    const float* bm   = (const float*)d_in[14];
    const float* Wk   = (const float*)d_in[15];
    const float* bk   = (const float*)d_in[16];
    const float* Wc1  = (const float*)d_in[17];
    const float* bc1  = (const float*)d_in[18];
    const float* Wc2  = (const float*)d_in[19];
    const float* bc2  = (const float*)d_in[20];
    const float* war  = (const float*)d_in[21];
    const float* bar  = (const float*)d_in[22];
    // d_in[23..26] (Wwc,bwc,waw,baw) dead: softmax over length-1 axis == 1.
    const float* Wwcat = (const float*)d_in[27];
    const float* bwcat = (const float*)d_in[28];

    float* S = nullptr;
    cudaGetSymbolAddress((void**)&S, g_s);

    float* outC = (float*)d_out;
    float* outM = (float*)d_out + (ll)NB * ND;
    const int D = ND, B = NB;

    // knowT
    {
        dim3 grid(7, 16, NB);
        transpose_k<<<grid, dim3(32, 8)>>>(know, S + OFF_KNOWT);
    }

    // q = tanh([question] @ Wsc + bsc), K=1024
    small_gemm(question, question, 2 * D, 2 * D, Wsc, Wsc, D, 1,
               S + OFF_Q, bsc, B, D, 2 * D, 0, ACT_TANH);
    // pa = q @ Wp + bp
    small_gemm(S + OFF_Q, S + OFF_Q, D, D, Wp, Wp, D, 1,
               S + OFF_PA, bp, B, D, D, 0, ACT_NONE);
    // cq = [control0 | pa] @ Wcq + bcq  (K=1024 split)
    small_gemm(control0, S + OFF_PA, D, D, Wcq, Wcq + (ll)D * D, D, 1,
               S + OFF_CQ, bcq, B, D, 2 * D, 0, ACT_NONE);
    // control (to output)
    attnc_kernel<<<B, 256>>>(words, S + OFF_CQ, wac, bac, outC);

    // pm = memory0 @ Wm + bm
    small_gemm(memory0, memory0, D, D, Wm, Wm, D, 1,
               S + OFF_PM, bm, B, D, D, 0, ACT_NONE);
    // WkW1b = Wk @ Wc1[D:2D]
    small_gemm(Wk, Wk, D, D, Wc1 + (ll)D * D, Wc1 + (ll)D * D, D, 1,
               S + OFF_WKW, nullptr, D, D, D, 0, ACT_NONE);
    // pmc = pm @ Wc1[2D:3D] + bc1 ; += bk @ Wc1[D:2D]
    small_gemm(S + OFF_PM, S + OFF_PM, D, D,
               Wc1 + (ll)2 * D * D, Wc1 + (ll)2 * D * D, D, 1,
               S + OFF_PMC, bc1, B, D, D, 0, ACT_NONE);
    kbd_kernel<<<2, 256>>>(Wc1, bk, S + OFF_KBD);
    addvec_kernel<<<(B * D) / 256, 256>>>(S + OFF_PMC, S + OFF_KBD);

    // v, c ; u = Wc2 applied to v
    vc_kernel<<<B, 256>>>(outC, war, bc2, bar, S + OFF_V, S + OFF_C);
    small_gemm(S + OFF_V, S + OFF_V, D, D, Wc2, Wc2, 1, D,
               S + OFF_U, nullptr, B, D, D, 0, ACT_NONE);

    // logit init with c[b]
    logit_init_kernel<<<(NM + 255) / 256, 256>>>(S + OFF_C, S + OFF_LOGIT);

    // HEAVY 1: spk = (knowT @ Wk + bk) * pm[b]   (M=50176, K=512)
    {
        dim3 grid(4, NM / 128);
        gemm_h<0><<<grid, 256>>>(S + OFF_KNOWT, S + OFF_KNOWT, Wk, Wk, 512,
                                 S + OFF_SPK, bk, S + OFF_PM,
                                 nullptr, nullptr, nullptr);
    }
    // HEAVY 2+3 fused: logit[m] += relu(spk@W1a + knowT@WkW1b + pmc[b]) . u[b]
    {
        dim3 grid(4, NM / 128);
        gemm_h<1><<<grid, 256>>>(S + OFF_SPK, S + OFF_KNOWT,
                                 Wc1, S + OFF_WKW, 1024,
                                 nullptr, nullptr, nullptr,
                                 S + OFF_PMC, S + OFF_U, S + OFF_LOGIT);
    }

    softmaxn_kernel<<<B, 256>>>(S + OFF_LOGIT, S + OFF_AR);
    read_kernel<<<B, 256>>>(know, S + OFF_AR, S + OFF_READ);

    // next_mem = [read | memory0] @ [Wwcat[:D] ; Wwcat[D:]+Wwcat[2D:]] + bwcat
    wsum_kernel<<<(D * D) / 256, 256>>>(Wwcat, S + OFF_WSUM);
    small_gemm(S + OFF_READ, memory0, D, D, Wwcat, S + OFF_WSUM, D, 1,
               outM, bwcat, B, D, 2 * D, 0, ACT_NONE);
}

// round 6
// speedup vs baseline: 2.9181x; 1.3838x over previous
#include <cuda_runtime.h>
#include <cuda_fp16.h>
#include <cstdint>

typedef long long ll;

#define NB 256
#define NS 32
#define ND 512
#define NHW 196
#define NM (NB*NHW)   // 50176

// --------------------- scratch layout (BYTE offsets) ----------------------
// "planes" buffers hold E fp16 hi values then E fp16 lo values (4E bytes).
#define B_Q      ((ll)0)           // planes E=131072
#define B_PA     ((ll)524288)      // planes E=131072
#define B_CQ     ((ll)1048576)     // fp32 131072
#define B_PMP    ((ll)1572864)     // planes E=131072
#define B_PMF    ((ll)2097152)     // fp32 131072
#define B_PMC    ((ll)2621440)     // fp32 131072
#define B_V      ((ll)3145728)     // planes E=131072
#define B_U      ((ll)3670016)     // fp32 131072
#define B_READ   ((ll)4194304)     // planes E=131072
#define B_C      ((ll)4718592)     // fp32 256
#define B_BIAS2  ((ll)4719616)     // fp32 512
#define B_LOGIT  ((ll)4721664)     // fp32 50176
#define B_AR     ((ll)4922368)     // fp32 50176
#define B_WKT    ((ll)5242880)     // planes E=262144
#define B_W1AT   ((ll)6291456)     // planes E=262144
#define B_WKWT   ((ll)7340032)     // planes E=262144
#define B_WSCT   ((ll)8388608)     // planes E=524288 (512x1024)
#define B_WPT    ((ll)10485760)    // planes E=262144
#define B_WCQT   ((ll)11534336)    // planes E=524288
#define B_WMT    ((ll)13631488)    // planes E=262144
#define B_WC1CT  ((ll)14680064)    // planes E=262144
#define B_NMBT   ((ll)15728640)    // planes E=524288 (512x1024)
#define B_W1BT   ((ll)17825792)    // planes E=262144
#define B_QR     ((ll)18874368)    // planes E=262144 (question)
#define B_C0R    ((ll)19922944)    // planes E=131072
#define B_M0R    ((ll)20447232)    // planes E=131072
#define B_WC2R   ((ll)20971520)    // planes E=262144
#define B_KNOWT  ((ll)22020096)    // planes E=25690112
#define B_SPK    ((ll)124780544)   // planes E=25690112
#define B_WKP    ((ll)227540992)   // planes E=262144 (Wk, ORIGINAL orientation)
#define B_TOTAL  ((ll)228589568)

__device__ __align__(1024) char g_s[B_TOTAL];

// ===================== arch-generic PTX helpers (sm_80+) ===================
__device__ __forceinline__ uint32_t smem_u32(const void* p) {
    uint32_t a;
    asm("{ .reg .u64 t; cvta.to.shared.u64 t, %1; cvt.u32.u64 %0, t; }"
        : "=r"(a) : "l"(p));
    return a;
}

#define CP16(dst, src) \
    asm volatile("cp.async.cg.shared.global [%0], [%1], 16;" :: "r"(dst), "l"(src) : "memory")
#define CP_COMMIT() asm volatile("cp.async.commit_group;" ::: "memory")
#define CP_WAIT1()  asm volatile("cp.async.wait_group 1;" ::: "memory")
#define CP_WAIT0()  asm volatile("cp.async.wait_group 0;" ::: "memory")

#define LDSM_X4(r0, r1, r2, r3, a) \
    asm volatile("ldmatrix.sync.aligned.m8n8.x4.shared.b16 {%0,%1,%2,%3}, [%4];" \
        : "=r"(r0), "=r"(r1), "=r"(r2), "=r"(r3) : "r"(a))

#define MMA16(d, a, b) \
    asm volatile("mma.sync.aligned.m16n8k16.row.col.f32.f16.f16.f32 " \
        "{%0,%1,%2,%3}, {%4,%5,%6,%7}, {%8,%9}, {%0,%1,%2,%3};" \
        : "+f"((d)[0]), "+f"((d)[1]), "+f"((d)[2]), "+f"((d)[3]) \
        : "r"((a)[0]), "r"((a)[1]), "r"((a)[2]), "r"((a)[3]), \
          "r"((b)[0]), "r"((b)[1]))

__device__ __forceinline__ void splitw(__half* hp, __half* lp, ll i, float v) {
    __half h = __float2half_rn(v);
    hp[i] = h;
    lp[i] = __float2half_rn(v - __half2float(h));
}
// paired (even-index) split store: one 4B store per plane
__device__ __forceinline__ void splitw2(__half* hp, __half* lp, ll i,
                                        float v0, float v1) {
    __half h0 = __float2half_rn(v0), h1 = __float2half_rn(v1);
    *(__half2*)(hp + i) = __halves2half2(h0, h1);
    *(__half2*)(lp + i) = __halves2half2(
        __float2half_rn(v0 - __half2float(h0)),
        __float2half_rn(v1 - __half2float(h1)));
}

struct Op { const __half* h; const __half* l; int ld; };

// ============ split-fp16 emulated-fp32 GEMM (128x128x32 tiles) =============
// acc[m,n] = sum_k A[m,k]*BT[n,k] with A,BT given as (hi,lo) fp16 planes.
// k<512 uses A1/B1; k>=512 uses A2/B2 (k-512).
// MODE 0: v = act(acc + bias[n]); if C store fp32; if Ch store split planes
// MODE 1: v = (acc + bias[n]) * aux[b*512+n], b=m/196; store split planes
// MODE 2: logit[m] += sum_n relu(acc + aux[b,n]) * uv[b,n]
// smem: 2 stages x 4 tiles (Ah,Al,Bh,Bl) x 128 rows x 80B + 512B rowsum.
#define SMB 82432

template<int MODE>
__global__ __launch_bounds__(512, 1)
void tc_gemm(Op A1, Op A2, Op B1, Op B2, int K,
             float* __restrict__ C, __half* __restrict__ Ch, __half* __restrict__ Cl,
             int ldc, const float* __restrict__ bias, int act,
             const float* __restrict__ aux, const float* __restrict__ uv,
             float* __restrict__ logit)
{
    extern __shared__ char smem[];
    const uint32_t su = smem_u32(smem);
    const int tid = threadIdx.x;
    const int lane = tid & 31, wid = tid >> 5;
    const int wm = wid & 3, wn = wid >> 2;
    const int m0 = blockIdx.y * 128, n0 = blockIdx.x * 128;
    const int NC = K >> 5;

    float acc[2][4][4];
#pragma unroll
    for (int i = 0; i < 2; i++)
#pragma unroll
        for (int j = 0; j < 4; j++)
#pragma unroll
            for (int r = 0; r < 4; r++) acc[i][j][r] = 0.f;

    const int crow = tid >> 2, cq = tid & 3;

    auto cp_chunk = [&](int c) {
        const int kk0 = c << 5;
        const Op Ao = (kk0 < 512) ? A1 : A2;
        const Op Bo = (kk0 < 512) ? B1 : B2;
        const int ko = kk0 & 511;
        const uint32_t st = su + (uint32_t)(c & 1) * 40960u;
        const uint32_t d0 = st + crow * 80u + cq * 16u;
        CP16(d0,           Ao.h + (ll)(m0 + crow) * Ao.ld + ko + cq * 8);
        CP16(d0 + 10240u,  Ao.l + (ll)(m0 + crow) * Ao.ld + ko + cq * 8);
        CP16(d0 + 20480u,  Bo.h + (ll)(n0 + crow) * Bo.ld + ko + cq * 8);
        CP16(d0 + 30720u,  Bo.l + (ll)(n0 + crow) * Bo.ld + ko + cq * 8);
        CP_COMMIT();
    };

    // ldmatrix per-thread base offsets (bytes within a tile)
    const uint32_t a_off =
        (uint32_t)(wm * 32 + (lane & 7) + ((lane >> 3) & 1) * 8) * 80u
        + (uint32_t)(lane >> 4) * 16u;
    const uint32_t b_off =
        (uint32_t)(wn * 32 + (lane & 7) + (lane >> 4) * 8) * 80u
        + (uint32_t)((lane >> 3) & 1) * 16u;

    cp_chunk(0);
    for (int c = 0; c < NC; c++) {
        if (c + 1 < NC) { cp_chunk(c + 1); CP_WAIT1(); }
        else            { CP_WAIT0(); }
        __syncthreads();
        const uint32_t sa = su + (uint32_t)(c & 1) * 40960u;
#pragma unroll
        for (int kk2 = 0; kk2 < 2; kk2++) {
            const uint32_t kof = (uint32_t)kk2 * 32u;
            uint32_t ah[2][4], al[2][4], bh[4][2], bl[4][2];
#pragma unroll
            for (int tm = 0; tm < 2; tm++) {
                LDSM_X4(ah[tm][0], ah[tm][1], ah[tm][2], ah[tm][3],
                        sa + a_off + tm * 1280u + kof);
                LDSM_X4(al[tm][0], al[tm][1], al[tm][2], al[tm][3],
                        sa + 10240u + a_off + tm * 1280u + kof);
            }
#pragma unroll
            for (int tp = 0; tp < 2; tp++) {
                uint32_t r0, r1, r2, r3;
                LDSM_X4(r0, r1, r2, r3, sa + 20480u + b_off + tp * 1280u + kof);
                bh[2*tp][0] = r0; bh[2*tp][1] = r1;
                bh[2*tp+1][0] = r2; bh[2*tp+1][1] = r3;
                LDSM_X4(r0, r1, r2, r3, sa + 30720u + b_off + tp * 1280u + kof);
                bl[2*tp][0] = r0; bl[2*tp][1] = r1;
                bl[2*tp+1][0] = r2; bl[2*tp+1][1] = r3;
            }
#pragma unroll
            for (int tm = 0; tm < 2; tm++)
#pragma unroll
                for (int tn = 0; tn < 4; tn++) {
                    MMA16(acc[tm][tn], ah[tm], bh[tn]);
                    MMA16(acc[tm][tn], ah[tm], bl[tn]);
                    MMA16(acc[tm][tn], al[tm], bh[tn]);
                }
        }
        __syncthreads();
    }

    float* rowsum = (float*)(smem + 81920);
    if (MODE == 2) {
        if (tid < 128) rowsum[tid] = 0.f;
        __syncthreads();
    }

#pragma unroll
    for (int tm = 0; tm < 2; tm++) {
        const int lr0 = wm * 32 + tm * 16 + (lane >> 2);
        const int r0 = m0 + lr0, r1 = r0 + 8;
        if (MODE == 0) {
#pragma unroll
            for (int tn = 0; tn < 4; tn++) {
                const int gn = n0 + wn * 32 + tn * 8 + (lane & 3) * 2;
                float v0 = acc[tm][tn][0], v1 = acc[tm][tn][1];
                float v2 = acc[tm][tn][2], v3 = acc[tm][tn][3];
                if (bias) {
                    float b0 = bias[gn], b1 = bias[gn + 1];
                    v0 += b0; v1 += b1; v2 += b0; v3 += b1;
                }
                if (act == 1) {
                    v0 = tanhf(v0); v1 = tanhf(v1);
                    v2 = tanhf(v2); v3 = tanhf(v3);
                }
                if (C) {
                    *(float2*)&C[(ll)r0 * ldc + gn] = make_float2(v0, v1);
                    *(float2*)&C[(ll)r1 * ldc + gn] = make_float2(v2, v3);
                }
                if (Ch) {
                    splitw2(Ch, Cl, (ll)r0 * ldc + gn, v0, v1);
                    splitw2(Ch, Cl, (ll)r1 * ldc + gn, v2, v3);
                }
            }
        } else if (MODE == 1) {
            const int b0 = r0 / NHW, b1 = r1 / NHW;
#pragma unroll
            for (int tn = 0; tn < 4; tn++) {
                const int gn = n0 + wn * 32 + tn * 8 + (lane & 3) * 2;
                const float bb0 = bias[gn], bb1 = bias[gn + 1];
                const float* a0 = aux + (ll)b0 * 512 + gn;
                const float* a1 = aux + (ll)b1 * 512 + gn;
                splitw2(Ch, Cl, (ll)r0 * 512 + gn,
                        (acc[tm][tn][0] + bb0) * a0[0],
                        (acc[tm][tn][1] + bb1) * a0[1]);
                splitw2(Ch, Cl, (ll)r1 * 512 + gn,
                        (acc[tm][tn][2] + bb0) * a1[0],
                        (acc[tm][tn][3] + bb1) * a1[1]);
            }
        } else {
            const int b0 = r0 / NHW, b1 = r1 / NHW;
            float p0 = 0.f, p1 = 0.f;
#pragma unroll
            for (int tn = 0; tn < 4; tn++) {
                const int gn = n0 + wn * 32 + tn * 8 + (lane & 3) * 2;
                const float* x0 = aux + (ll)b0 * 512 + gn;
                const float* u0 = uv  + (ll)b0 * 512 + gn;
                const float* x1 = aux + (ll)b1 * 512 + gn;
                const float* u1 = uv  + (ll)b1 * 512 + gn;
                p0 += fmaxf(acc[tm][tn][0] + x0[0], 0.f) * u0[0]
                    + fmaxf(acc[tm][tn][1] + x0[1], 0.f) * u0[1];
                p1 += fmaxf(acc[tm][tn][2] + x1[0], 0.f) * u1[0]
                    + fmaxf(acc[tm][tn][3] + x1[1], 0.f) * u1[1];
            }
            p0 += __shfl_xor_sync(0xffffffffu, p0, 1);
            p0 += __shfl_xor_sync(0xffffffffu, p0, 2);
            p1 += __shfl_xor_sync(0xffffffffu, p1, 1);
            p1 += __shfl_xor_sync(0xffffffffu, p1, 2);
            if ((lane & 3) == 0) {
                atomicAdd(&rowsum[lr0], p0);
                atomicAdd(&rowsum[lr0 + 8], p1);
            }
        }
    }
    if (MODE == 2) {
        __syncthreads();
        if (tid < 128) atomicAdd(&logit[m0 + tid], rowsum[tid]);
    }
}

// ===================== transposes & split producers ========================
__global__ __launch_bounds__(256)
void transpose_k(const float* __restrict__ know, __half* __restrict__ kh,
                 __half* __restrict__ kl)
{
    __shared__ float t[32][33];
    const int b = blockIdx.z;
    const int n0 = blockIdx.x * 32, d0 = blockIdx.y * 32;
    const int tx = threadIdx.x, ty = threadIdx.y;
#pragma unroll
    for (int r = 0; r < 32; r += 8) {
        int d = d0 + ty + r, n = n0 + tx;
        float v = 0.f;
        if (n < NHW) v = know[((ll)b * ND + d) * NHW + n];
        t[ty + r][tx] = v;
    }
    __syncthreads();
#pragma unroll
    for (int r = 0; r < 32; r += 8) {
        int n = n0 + ty + r, d = d0 + tx;
        if (n < NHW) splitw(kh, kl, ((ll)b * NHW + n) * ND + d, t[tx][ty + r]);
    }
}

struct TDesc { const float* src; __half* dh; int R; int ldd; };
struct TBatch { TDesc d[9]; };

// dst[n,k] = src[k,n] split into planes; src [R,512] row-major; n < 512.
__global__ __launch_bounds__(256)
void trans_w(TBatch tb)
{
    const TDesc td = tb.d[blockIdx.z];
    const int k0 = blockIdx.y * 32, n0 = blockIdx.x * 32;
    if (k0 >= td.R) return;
    __half* dl = td.dh + (ll)512 * td.ldd;
    __shared__ float t[32][33];
    const int tx = threadIdx.x, ty = threadIdx.y;
#pragma unroll
    for (int r = 0; r < 32; r += 8)
        t[ty + r][tx] = td.src[(ll)(k0 + ty + r) * 512 + n0 + tx];
    __syncthreads();
#pragma unroll
    for (int r = 0; r < 32; r += 8)
        splitw(td.dh, dl, (ll)(n0 + ty + r) * td.ldd + k0 + tx, t[tx][ty + r]);
}

__global__ void wsumT_kernel(const float* __restrict__ Wwcat,
                             __half* __restrict__ nh)
{
    int i = blockIdx.x * 256 + threadIdx.x;
    int k = i & 511, n = i >> 9;
    float v = Wwcat[(ll)(512 + k) * 512 + n] + Wwcat[(ll)(1024 + k) * 512 + n];
    splitw(nh, nh + 524288, (ll)n * 1024 + 512 + k, v);
}

__global__ void bias2_kernel(const float* __restrict__ Wc1, const float* __restrict__ bk,
                             const float* __restrict__ bc1, float* __restrict__ b2)
{
    int d = blockIdx.x * 256 + threadIdx.x;
    float acc = bc1[d];
    for (int e = 0; e < ND; e++) acc += bk[e] * Wc1[(ll)(512 + e) * 512 + d];
    b2[d] = acc;
}

// split copies: question | control0 | memory0 | Wc2 | Wk(original orientation)
__global__ void copy_split(const float* __restrict__ q, const float* __restrict__ c0,
                           const float* __restrict__ m0, const float* __restrict__ wc2,
                           const float* __restrict__ wk,
                           char* __restrict__ Sb)
{
    int i = blockIdx.x * 256 + threadIdx.x;
    if (i < 262144) {
        __half* h = (__half*)(Sb + B_QR);
        splitw(h, h + 262144, i, q[i]);
    } else if (i < 393216) {
        __half* h = (__half*)(Sb + B_C0R);
        splitw(h, h + 131072, i - 262144, c0[i - 262144]);
    } else if (i < 524288) {
        __half* h = (__half*)(Sb + B_M0R);
        splitw(h, h + 131072, i - 393216, m0[i - 393216]);
    } else if (i < 786432) {
        __half* h = (__half*)(Sb + B_WC2R);
        splitw(h, h + 262144, i - 524288, wc2[i - 524288]);
    } else {
        __half* h = (__half*)(Sb + B_WKP);
        splitw(h, h + 262144, i - 786432, wk[i - 786432]);
    }
}

__global__ void logit_init_kernel(const float* __restrict__ c, float* __restrict__ logit)
{
    int i = blockIdx.x * 256 + threadIdx.x;
    logit[i] = c[i / NHW];
}

// ===================== attention / reductions ==============================
__global__ __launch_bounds__(256)
void attnc_kernel(const float* __restrict__ words, const float* __restrict__ cq,
                  const float* __restrict__ wac, const float* __restrict__ bac,
                  float* __restrict__ control)
{
    const int b = blockIdx.x, tid = threadIdx.x;
    const int warp = tid >> 5, lane = tid & 31;
    __shared__ float cw[ND];
    __shared__ float sa[NS];
    for (int d = tid; d < ND; d += 256) cw[d] = cq[(ll)b * ND + d] * wac[d];
    __syncthreads();
#pragma unroll
    for (int r = 0; r < 4; r++) {
        int s = warp * 4 + r;
        const float* wp = words + ((ll)b * NS + s) * ND;
        float acc = 0.f;
        for (int d = lane; d < ND; d += 32) acc += cw[d] * wp[d];
#pragma unroll
        for (int o = 16; o; o >>= 1) acc += __shfl_xor_sync(0xffffffffu, acc, o);
        if (lane == 0) sa[s] = acc + bac[0];
    }
    __syncthreads();
    if (warp == 0) {
        float v = sa[lane], mx = v;
#pragma unroll
        for (int o = 16; o; o >>= 1) mx = fmaxf(mx, __shfl_xor_sync(0xffffffffu, mx, o));
        float e = expf(v - mx), sm = e;
#pragma unroll
        for (int o = 16; o; o >>= 1) sm += __shfl_xor_sync(0xffffffffu, sm, o);
        sa[lane] = e / sm;
    }
    __syncthreads();
    for (int d = tid; d < ND; d += 256) {
        float acc = 0.f;
#pragma unroll 8
        for (int s = 0; s < NS; s++) acc += sa[s] * words[((ll)b * NS + s) * ND + d];
        control[(ll)b * ND + d] = acc;
    }
}

__global__ __launch_bounds__(256)
void vc_kernel(const float* __restrict__ control, const float* __restrict__ war,
               const float* __restrict__ bc2, const float* __restrict__ bar,
               __half* __restrict__ vh, float* __restrict__ c)
{
    const int b = blockIdx.x, tid = threadIdx.x;
    __shared__ float s[256];
    float p = 0.f;
    for (int d = tid; d < ND; d += 256) {
        float vv = control[(ll)b * ND + d] * war[d];
        splitw(vh, vh + 131072, (ll)b * ND + d, vv);
        p += bc2[d] * vv;
    }
    s[tid] = p; __syncthreads();
    for (int o = 128; o; o >>= 1) { if (tid < o) s[tid] += s[tid + o]; __syncthreads(); }
    if (tid == 0) c[b] = s[0] + bar[0];
}

__global__ __launch_bounds__(256)
void softmaxn_kernel(const float* __restrict__ logit, float* __restrict__ ar)
{
    const int b = blockIdx.x, tid = threadIdx.x;
    __shared__ float s[256];
    float v = (tid < NHW) ? logit[(ll)b * NHW + tid] : -1e30f;
    s[tid] = v; __syncthreads();
    for (int o = 128; o; o >>= 1) { if (tid < o) s[tid] = fmaxf(s[tid], s[tid + o]); __syncthreads(); }
    float mx = s[0]; __syncthreads();
    float e = (tid < NHW) ? expf(v - mx) : 0.f;
    s[tid] = e; __syncthreads();
    for (int o = 128; o; o >>= 1) { if (tid < o) s[tid] += s[tid + o]; __syncthreads(); }
    float sum = s[0];
    if (tid < NHW) ar[(ll)b * NHW + tid] = e / sum;
}

__global__ __launch_bounds__(256)
void read_kernel(const float* __restrict__ know, const float* __restrict__ ar,
                 __half* __restrict__ rh)
{
    const int b = blockIdx.x, tid = threadIdx.x;
    const int warp = tid >> 5, lane = tid & 31;
    __shared__ float s[NHW];
    if (tid < NHW) s[tid] = ar[(ll)b * NHW + tid];
    __syncthreads();
    for (int d = warp; d < ND; d += 8) {
        const float* kp = know + ((ll)b * ND + d) * NHW;
        float acc = 0.f;
        for (int n = lane; n < NHW; n += 32) acc += kp[n] * s[n];
#pragma unroll
        for (int o = 16; o; o >>= 1) acc += __shfl_xor_sync(0xffffffffu, acc, o);
        if (lane == 0) splitw(rh, rh + 131072, (ll)b * ND + d, acc);
    }
}

// ===========================================================================
extern "C" void kernel_launch(void* const* d_in, const int* in_sizes, int n_in,
                              void* d_out, int out_size)
{
    const float* words    = (const float*)d_in[0];
    const float* question = (const float*)d_in[1];
    const float* know     = (const float*)d_in[2];
    const float* control0 = (const float*)d_in[3];
    const float* memory0  = (const float*)d_in[4];
    const float* Wsc  = (const float*)d_in[5];
    const float* bsc  = (const float*)d_in[6];
    const float* Wp   = (const float*)d_in[7];
    const float* bp   = (const float*)d_in[8];
    const float* Wcq  = (const float*)d_in[9];
    const float* bcq  = (const float*)d_in[10];
    const float* wac  = (const float*)d_in[11];
    const float* bac  = (const float*)d_in[12];
    const float* Wm   = (const float*)d_in[13];
    const float* bm   = (const float*)d_in[14];
    const float* Wk   = (const float*)d_in[15];
    const float* bk   = (const float*)d_in[16];
    const float* Wc1  = (const float*)d_in[17];
    const float* bc1  = (const float*)d_in[18];
    const float* Wc2  = (const float*)d_in[19];
    const float* bc2  = (const float*)d_in[20];
    const float* war  = (const float*)d_in[21];
    const float* bar  = (const float*)d_in[22];
    // d_in[23..26] dead: softmax over length-1 axis == 1 -> attn_mem == memory0
    const float* Wwcat = (const float*)d_in[27];
    const float* bwcat = (const float*)d_in[28];

    cudaFuncSetAttribute(tc_gemm<0>, cudaFuncAttributeMaxDynamicSharedMemorySize, SMB);
    cudaFuncSetAttribute(tc_gemm<1>, cudaFuncAttributeMaxDynamicSharedMemorySize, SMB);
    cudaFuncSetAttribute(tc_gemm<2>, cudaFuncAttributeMaxDynamicSharedMemorySize, SMB);

    char* Sb = nullptr;
    cudaGetSymbolAddress((void**)&Sb, g_s);

    float* outC = (float*)d_out;
    float* outM = (float*)d_out + (ll)NB * ND;

    auto F  = [&](ll off) { return (float*)(Sb + off); };
    auto Hh = [&](ll off) { return (__half*)(Sb + off); };
    auto OP = [&](ll off, ll E, int ld, ll ko) -> Op {
        __half* h = (__half*)(Sb + off);
        return { h + ko, h + E + ko, ld };
    };
    Op Z = { nullptr, nullptr, 0 };

    // 1) weight transposes -> split planes
    {
        TBatch tb;
        tb.d[0] = { Wk,                     Hh(B_WKT),   512, 512 };
        tb.d[1] = { Wc1,                    Hh(B_W1AT),  512, 512 };
        tb.d[2] = { Wc1 + (ll)ND * ND,      Hh(B_W1BT),  512, 512 };
        tb.d[3] = { Wsc,                    Hh(B_WSCT), 1024, 1024 };
        tb.d[4] = { Wp,                     Hh(B_WPT),   512, 512 };
        tb.d[5] = { Wcq,                    Hh(B_WCQT), 1024, 1024 };
        tb.d[6] = { Wm,                     Hh(B_WMT),   512, 512 };
        tb.d[7] = { Wc1 + (ll)2 * ND * ND,  Hh(B_WC1CT), 512, 512 };
        tb.d[8] = { Wwcat,                  Hh(B_NMBT),  512, 1024 };
        trans_w<<<dim3(16, 32, 9), dim3(32, 8)>>>(tb);
    }
    // 2) knowT split planes
    transpose_k<<<dim3(7, 16, NB), dim3(32, 8)>>>(know, Hh(B_KNOWT),
                                                  Hh(B_KNOWT) + 25690112);
    // 3) summed second half of next_mem B
    wsumT_kernel<<<1024, 256>>>(Wwcat, Hh(B_NMBT));
    // 4) bias2 = bc1 + bk @ Wc1[D:2D]
    bias2_kernel<<<2, 256>>>(Wc1, bk, bc1, F(B_BIAS2));
    // 5) split copies of direct operands (incl. Wk original orientation)
    copy_split<<<4096, 256>>>(question, control0, memory0, Wc2, Wk, Sb);

    // 6) q = tanh(question @ Wsc + bsc)  [K=1024] -> planes
    tc_gemm<0><<<dim3(4, 2), 512, SMB>>>(
        OP(B_QR, 262144, 1024, 0), OP(B_QR, 262144, 1024, 512),
        OP(B_WSCT, 524288, 1024, 0), OP(B_WSCT, 524288, 1024, 512), 1024,
        nullptr, Hh(B_Q), Hh(B_Q) + 131072, 512, bsc, 1,
        nullptr, nullptr, nullptr);
    // 7) pm = memory0 @ Wm + bm -> fp32 + planes
    tc_gemm<0><<<dim3(4, 2), 512, SMB>>>(
        OP(B_M0R, 131072, 512, 0), Z, OP(B_WMT, 262144, 512, 0), Z, 512,
        F(B_PMF), Hh(B_PMP), Hh(B_PMP) + 131072, 512, bm, 0,
        nullptr, nullptr, nullptr);
    // 8) HEAVY 1: spk = (knowT @ Wk + bk) * pm[b] -> planes
    tc_gemm<1><<<dim3(4, NM / 128), 512, SMB>>>(
        OP(B_KNOWT, 25690112, 512, 0), Z, OP(B_WKT, 262144, 512, 0), Z, 512,
        nullptr, Hh(B_SPK), Hh(B_SPK) + 25690112, 512, bk, 0,
        F(B_PMF), nullptr, nullptr);
    // 9) WKWT[m,n] = sum_e W1bT[m,e] * Wk[n,e]  (Wk ORIGINAL orientation!)
    //    -> read by heavy2 as BT[n,dd] = sum_e Wc1[D+e,n]*Wk[dd,e]  ✓
    tc_gemm<0><<<dim3(4, 4), 512, SMB>>>(
        OP(B_W1BT, 262144, 512, 0), Z, OP(B_WKP, 262144, 512, 0), Z, 512,
        nullptr, Hh(B_WKWT), Hh(B_WKWT) + 262144, 512, nullptr, 0,
        nullptr, nullptr, nullptr);
    // 10) pa = q @ Wp + bp -> planes
    tc_gemm<0><<<dim3(4, 2), 512, SMB>>>(
        OP(B_Q, 131072, 512, 0), Z, OP(B_WPT, 262144, 512, 0), Z, 512,
        nullptr, Hh(B_PA), Hh(B_PA) + 131072, 512, bp, 0,
        nullptr, nullptr, nullptr);
    // 11) cq = [control0 | pa] @ Wcq + bcq  [K=1024] -> fp32
    tc_gemm<0><<<dim3(4, 2), 512, SMB>>>(
        OP(B_C0R, 131072, 512, 0), OP(B_PA, 131072, 512, 0),
        OP(B_WCQT, 524288, 1024, 0), OP(B_WCQT, 524288, 1024, 512), 1024,
        F(B_CQ), nullptr, nullptr, 512, bcq, 0,
        nullptr, nullptr, nullptr);
    // 12) control -> output
    attnc_kernel<<<NB, 256>>>(words, F(B_CQ), wac, bac, outC);
    // 13) v = control*war (planes); c = bc2.v + bar
    vc_kernel<<<NB, 256>>>(outC, war, bc2, bar, Hh(B_V), F(B_C));
    // 14) u = v @ Wc2 (contraction over 2nd index of Wc2) -> fp32
    tc_gemm<0><<<dim3(4, 2), 512, SMB>>>(
        OP(B_V, 131072, 512, 0), Z, OP(B_WC2R, 262144, 512, 0), Z, 512,
        F(B_U), nullptr, nullptr, 512, nullptr, 0,
        nullptr, nullptr, nullptr);
    // 15) pmc = pm @ Wc1[2D:3D] + bias2 -> fp32
    tc_gemm<0><<<dim3(4, 2), 512, SMB>>>(
        OP(B_PMP, 131072, 512, 0), Z, OP(B_WC1CT, 262144, 512, 0), Z, 512,
        F(B_PMC), nullptr, nullptr, 512, F(B_BIAS2), 0,
        nullptr, nullptr, nullptr);
    // 16) logit init with c[b]
    logit_init_kernel<<<NM / 256, 256>>>(F(B_C), F(B_LOGIT));
    // 17) HEAVY 2: logit[m] += relu(spk@W1a + knowT@WkW1b + pmc[b]) . u[b]
    tc_gemm<2><<<dim3(4, NM / 128), 512, SMB>>>(
        OP(B_SPK, 25690112, 512, 0), OP(B_KNOWT, 25690112, 512, 0),
        OP(B_W1AT, 262144, 512, 0), OP(B_WKWT, 262144, 512, 0), 1024,
        nullptr, nullptr, nullptr, 512, nullptr, 0,
        F(B_PMC), F(B_U), F(B_LOGIT));
    // 18-19) softmax over n, read (split planes)
    softmaxn_kernel<<<NB, 256>>>(F(B_LOGIT), F(B_AR));
    read_kernel<<<NB, 256>>>(know, F(B_AR), Hh(B_READ));
    // 20) next_mem = [read | memory0] @ nmBT^T + bwcat -> output fp32
    tc_gemm<0><<<dim3(4, 2), 512, SMB>>>(
        OP(B_READ, 131072, 512, 0), OP(B_M0R, 131072, 512, 0),
        OP(B_NMBT, 524288, 1024, 0), OP(B_NMBT, 524288, 1024, 512), 1024,
        outM, nullptr, nullptr, 512, bwcat, 0,
        nullptr, nullptr, nullptr);
}

// round 7
// speedup vs baseline: 4.3119x; 1.4776x over previous
#include <cuda_runtime.h>
#include <cuda_fp16.h>
#include <cstdint>

typedef long long ll;

#define NB 256
#define NS 32
#define ND 512
#define NHW 196
#define NM (NB*NHW)   // 50176

// --------------------- scratch layout (BYTE offsets) ----------------------
// "planes" buffers hold E fp16 hi values then E fp16 lo values (4E bytes).
// All GEMM-operand planes are stored TILED: [rowtile128][kchunk32][128r][64B]
// with quad swizzle q' = q ^ ((r>>1)&3) inside each 64B row.
#define B_Q      ((ll)0)           // planes E=131072
#define B_PA     ((ll)524288)      // planes E=131072
#define B_CQ     ((ll)1048576)     // fp32 131072
#define B_PMP    ((ll)1572864)     // planes E=131072
#define B_PMF    ((ll)2097152)     // fp32 131072
#define B_PMC    ((ll)2621440)     // fp32 131072
#define B_V      ((ll)3145728)     // planes E=131072
#define B_U      ((ll)3670016)     // fp32 131072
#define B_READ   ((ll)4194304)     // planes E=131072
#define B_C      ((ll)4718592)     // fp32 256
#define B_BIAS2  ((ll)4719616)     // fp32 512
#define B_LOGIT  ((ll)4721664)     // fp32 50176
#define B_AR     ((ll)4922368)     // fp32 50176
#define B_WKT    ((ll)5242880)     // planes E=262144
#define B_W1AT   ((ll)6291456)     // planes E=262144
#define B_WKWT   ((ll)7340032)     // planes E=262144
#define B_WSCT   ((ll)8388608)     // planes E=524288 (rows512, K1024)
#define B_WPT    ((ll)10485760)    // planes E=262144
#define B_WCQT   ((ll)11534336)    // planes E=524288
#define B_WMT    ((ll)13631488)    // planes E=262144
#define B_WC1CT  ((ll)14680064)    // planes E=262144
#define B_NMBT   ((ll)15728640)    // planes E=524288 (rows512, K1024)
#define B_W1BT   ((ll)17825792)    // planes E=262144
#define B_QR     ((ll)18874368)    // planes E=262144 (question, K1024)
#define B_C0R    ((ll)19922944)    // planes E=131072
#define B_M0R    ((ll)20447232)    // planes E=131072
#define B_WC2R   ((ll)20971520)    // planes E=262144
#define B_KNOWT  ((ll)22020096)    // planes E=25690112
#define B_SPK    ((ll)124780544)   // planes E=25690112
#define B_WKP    ((ll)227540992)   // planes E=262144 (Wk original orientation)
#define B_TOTAL  ((ll)228589568)

__device__ __align__(1024) char g_s[B_TOTAL];

// ===================== arch-generic PTX helpers (sm_80/90 core) ============
__device__ __forceinline__ uint32_t smem_u32(const void* p) {
    uint32_t a;
    asm("{ .reg .u64 t; cvta.to.shared.u64 t, %1; cvt.u32.u64 %0, t; }"
        : "=r"(a) : "l"(p));
    return a;
}

#define MBARRIER_INIT(addr, cnt) \
    asm volatile("mbarrier.init.shared.b64 [%0], %1;" :: "r"(addr), "r"(cnt) : "memory")
#define MBARRIER_ARRIVE(addr) \
    asm volatile("mbarrier.arrive.shared.b64 _, [%0];" :: "r"(addr) : "memory")
#define MBARRIER_EXPECT_TX(addr, bytes) \
    asm volatile("mbarrier.arrive.expect_tx.shared.b64 _, [%0], %1;" \
                 :: "r"(addr), "r"(bytes) : "memory")
#define MBARRIER_WAIT_PARITY(addr, par) do { \
    uint32_t _m = (addr), _p = (par), _d; \
    asm volatile("{ .reg .pred p; mbarrier.try_wait.parity.acquire.cta.shared::cta.b64 p, [%1], %2;" \
                 " selp.b32 %0,1,0,p; }" : "=r"(_d) : "r"(_m), "r"(_p) : "memory"); \
    if (!_d) { \
        asm volatile("{ .reg .pred P1; WL_%=:" \
                     " mbarrier.try_wait.parity.acquire.cta.shared::cta.b64 P1, [%0], %1, 0x989680;" \
                     " @P1 bra.uni WD_%=; bra.uni WL_%=; WD_%=: }" \
                     :: "r"(_m), "r"(_p) : "memory"); \
    } \
} while (0)
#define FENCE_ASYNC() asm volatile("fence.proxy.async.shared::cta;" ::: "memory")

// 1D bulk DMA global->shared with transaction-count completion (sm_90 core).
#define BULK_G2S(dst, src, bytes, mbar) \
    asm volatile("cp.async.bulk.shared::cluster.global.mbarrier::complete_tx::bytes " \
                 "[%0], [%1], %2, [%3];" \
                 :: "r"(dst), "l"(src), "r"(bytes), "r"(mbar) : "memory")

#define LDSM_X4(r0, r1, r2, r3, a) \
    asm volatile("ldmatrix.sync.aligned.m8n8.x4.shared.b16 {%0,%1,%2,%3}, [%4];" \
        : "=r"(r0), "=r"(r1), "=r"(r2), "=r"(r3) : "r"(a))

#define MMA16(d, a, b) \
    asm volatile("mma.sync.aligned.m16n8k16.row.col.f32.f16.f16.f32 " \
        "{%0,%1,%2,%3}, {%4,%5,%6,%7}, {%8,%9}, {%0,%1,%2,%3};" \
        : "+f"((d)[0]), "+f"((d)[1]), "+f"((d)[2]), "+f"((d)[3]) \
        : "r"((a)[0]), "r"((a)[1]), "r"((a)[2]), "r"((a)[3]), \
          "r"((b)[0]), "r"((b)[1]))

// element offset (in halves) inside a tiled-swizzled plane with kc chunks
__device__ __forceinline__ ll toff(int row, int k, int kc) {
    int r = row & 127;
    int quad = ((k >> 3) & 3) ^ ((r >> 1) & 3);
    return ((ll)((row >> 7) * kc + (k >> 5)) * 128 + r) * 32 + quad * 8 + (k & 7);
}

__device__ __forceinline__ void splitw_t(__half* hp, __half* lp, int row, int k,
                                         int kc, float v) {
    ll i = toff(row, k, kc);
    __half h = __float2half_rn(v);
    hp[i] = h;
    lp[i] = __float2half_rn(v - __half2float(h));
}
// paired (even k) split store
__device__ __forceinline__ void splitw2_t(__half* hp, __half* lp, int row, int k,
                                          int kc, float v0, float v1) {
    ll i = toff(row, k, kc);
    __half h0 = __float2half_rn(v0), h1 = __float2half_rn(v1);
    *(__half2*)(hp + i) = __halves2half2(h0, h1);
    *(__half2*)(lp + i) = __halves2half2(
        __float2half_rn(v0 - __half2float(h0)),
        __float2half_rn(v1 - __half2float(h1)));
}

struct Op { const __half* h; const __half* l; int kc; };

// ============ split-fp16 emulated-fp32 GEMM, bulk-DMA pipeline =============
// acc[m,n] = sum_k A[m,k]*BT[n,k]; A chunks: c < A1.kc -> A1, else A2. B same.
// MODE 0: v = act(acc+bias[n]); C fp32 and/or (Ch,Cl) tiled planes (okc)
// MODE 1: v = (acc+bias[n])*aux[b*512+n], b=m/196 -> tiled planes
// MODE 2: logit[m] += sum_n relu(acc+aux[b,n])*uv[b,n]
// smem: 4 stages x (Ah|Al|Bh|Bl 8KB each) = 128KB, mbarriers, rowsum.
#define SMB 131712

template<int MODE>
__global__ __launch_bounds__(512, 1)
void tc_gemm(Op A1, Op A2, Op B1, Op B2, int K,
             float* __restrict__ C, __half* __restrict__ Ch, __half* __restrict__ Cl,
             int ldc, int okc, const float* __restrict__ bias, int act,
             const float* __restrict__ aux, const float* __restrict__ uv,
             float* __restrict__ logit)
{
    extern __shared__ char smem[];
    const uint32_t su = smem_u32(smem);
    const int tid = threadIdx.x;
    const int lane = tid & 31, wid = tid >> 5;
    const int wm = wid & 3, wn = wid >> 2;
    const int m0 = blockIdx.y * 128, n0 = blockIdx.x * 128;
    const int NC = K >> 5;
    const uint32_t mbF = su + 131072u, mbE = su + 131104u;

    if (tid == 0) {
#pragma unroll
        for (int s = 0; s < 4; s++) {
            MBARRIER_INIT(mbF + s * 8, 1);
            MBARRIER_INIT(mbE + s * 8, 16);
        }
        FENCE_ASYNC();
    }
    __syncthreads();

    auto issue = [&](int cn) {
        const bool a1 = cn < A1.kc, b1 = cn < B1.kc;
        const __half* ah = a1 ? A1.h : A2.h;
        const __half* al = a1 ? A1.l : A2.l;
        const __half* bh = b1 ? B1.h : B2.h;
        const __half* bl = b1 ? B1.l : B2.l;
        const int ca = a1 ? cn : cn - A1.kc;
        const int cb = b1 ? cn : cn - B1.kc;
        const int kca = a1 ? A1.kc : A2.kc;
        const int kcb = b1 ? B1.kc : B2.kc;
        const ll ao = ((ll)((m0 >> 7) * kca + ca)) * 8192;
        const ll bo = ((ll)((n0 >> 7) * kcb + cb)) * 8192;
        const uint32_t st = su + (uint32_t)(cn & 3) * 32768u;
        const uint32_t mb = mbF + (cn & 3) * 8;
        MBARRIER_EXPECT_TX(mb, 32768u);
        BULK_G2S(st,           (const char*)ah + ao, 8192u, mb);
        BULK_G2S(st + 8192u,   (const char*)al + ao, 8192u, mb);
        BULK_G2S(st + 16384u,  (const char*)bh + bo, 8192u, mb);
        BULK_G2S(st + 24576u,  (const char*)bl + bo, 8192u, mb);
    };

    if (tid == 0) { issue(0); if (NC > 1) issue(1); if (NC > 2) issue(2); }

    // per-thread ldmatrix row bases + swizzle keys
    int ba[2], sa2[2], bb[2], sb2[2];
#pragma unroll
    for (int tm = 0; tm < 2; tm++) {
        int r = wm * 32 + tm * 16 + (lane & 7) + ((lane >> 3) & 1) * 8;
        ba[tm] = r * 64; sa2[tm] = (r >> 1) & 3;
    }
#pragma unroll
    for (int tp = 0; tp < 2; tp++) {
        int r = wn * 32 + tp * 16 + (lane & 7) + (lane >> 4) * 8;
        bb[tp] = r * 64; sb2[tp] = (r >> 1) & 3;
    }
    const int qa = lane >> 4, qb = (lane >> 3) & 1;

    float acc[2][4][4];
#pragma unroll
    for (int i = 0; i < 2; i++)
#pragma unroll
        for (int j = 0; j < 4; j++)
#pragma unroll
            for (int r = 0; r < 4; r++) acc[i][j][r] = 0.f;

    for (int c = 0; c < NC; c++) {
        if (tid == 0 && c + 3 < NC) {
            const int cn = c + 3;
            if (cn >= 4)
                MBARRIER_WAIT_PARITY(mbE + (cn & 3) * 8, ((cn >> 2) - 1) & 1);
            issue(cn);
        }
        MBARRIER_WAIT_PARITY(mbF + (c & 3) * 8, (c >> 2) & 1);
        const uint32_t st = su + (uint32_t)(c & 3) * 32768u;
#pragma unroll
        for (int kk2 = 0; kk2 < 2; kk2++) {
            uint32_t ah[2][4], al[2][4], bh[4][2], bl[4][2];
#pragma unroll
            for (int tm = 0; tm < 2; tm++) {
                const uint32_t ad = st + ba[tm]
                    + (uint32_t)((((qa + kk2 * 2) ^ sa2[tm]) & 3) * 16);
                LDSM_X4(ah[tm][0], ah[tm][1], ah[tm][2], ah[tm][3], ad);
                LDSM_X4(al[tm][0], al[tm][1], al[tm][2], al[tm][3], ad + 8192u);
            }
#pragma unroll
            for (int tp = 0; tp < 2; tp++) {
                const uint32_t bd = st + 16384u + bb[tp]
                    + (uint32_t)((((qb + kk2 * 2) ^ sb2[tp]) & 3) * 16);
                uint32_t r0, r1, r2, r3;
                LDSM_X4(r0, r1, r2, r3, bd);
                bh[2*tp][0] = r0; bh[2*tp][1] = r1;
                bh[2*tp+1][0] = r2; bh[2*tp+1][1] = r3;
                LDSM_X4(r0, r1, r2, r3, bd + 8192u);
                bl[2*tp][0] = r0; bl[2*tp][1] = r1;
                bl[2*tp+1][0] = r2; bl[2*tp+1][1] = r3;
            }
#pragma unroll
            for (int tm = 0; tm < 2; tm++)
#pragma unroll
                for (int tn = 0; tn < 4; tn++) {
                    MMA16(acc[tm][tn], ah[tm], bh[tn]);
                    MMA16(acc[tm][tn], ah[tm], bl[tn]);
                    MMA16(acc[tm][tn], al[tm], bh[tn]);
                }
        }
        if (lane == 0) MBARRIER_ARRIVE(mbE + (c & 3) * 8);
    }

    float* rowsum = (float*)(smem + 131136);
    if (MODE == 2) {
        __syncthreads();
        if (tid < 128) rowsum[tid] = 0.f;
        __syncthreads();
    }

#pragma unroll
    for (int tm = 0; tm < 2; tm++) {
        const int lr0 = wm * 32 + tm * 16 + (lane >> 2);
        const int r0 = m0 + lr0, r1 = r0 + 8;
        if (MODE == 0) {
#pragma unroll
            for (int tn = 0; tn < 4; tn++) {
                const int gn = n0 + wn * 32 + tn * 8 + (lane & 3) * 2;
                float v0 = acc[tm][tn][0], v1 = acc[tm][tn][1];
                float v2 = acc[tm][tn][2], v3 = acc[tm][tn][3];
                if (bias) {
                    float b0 = bias[gn], b1 = bias[gn + 1];
                    v0 += b0; v1 += b1; v2 += b0; v3 += b1;
                }
                if (act == 1) {
                    v0 = tanhf(v0); v1 = tanhf(v1);
                    v2 = tanhf(v2); v3 = tanhf(v3);
                }
                if (C) {
                    *(float2*)&C[(ll)r0 * ldc + gn] = make_float2(v0, v1);
                    *(float2*)&C[(ll)r1 * ldc + gn] = make_float2(v2, v3);
                }
                if (Ch) {
                    splitw2_t(Ch, Cl, r0, gn, okc, v0, v1);
                    splitw2_t(Ch, Cl, r1, gn, okc, v2, v3);
                }
            }
        } else if (MODE == 1) {
            const int b0 = r0 / NHW, b1 = r1 / NHW;
#pragma unroll
            for (int tn = 0; tn < 4; tn++) {
                const int gn = n0 + wn * 32 + tn * 8 + (lane & 3) * 2;
                const float bb0 = bias[gn], bb1 = bias[gn + 1];
                const float* a0 = aux + (ll)b0 * 512 + gn;
                const float* a1 = aux + (ll)b1 * 512 + gn;
                splitw2_t(Ch, Cl, r0, gn, okc,
                          (acc[tm][tn][0] + bb0) * a0[0],
                          (acc[tm][tn][1] + bb1) * a0[1]);
                splitw2_t(Ch, Cl, r1, gn, okc,
                          (acc[tm][tn][2] + bb0) * a1[0],
                          (acc[tm][tn][3] + bb1) * a1[1]);
            }
        } else {
            const int b0 = r0 / NHW, b1 = r1 / NHW;
            float p0 = 0.f, p1 = 0.f;
#pragma unroll
            for (int tn = 0; tn < 4; tn++) {
                const int gn = n0 + wn * 32 + tn * 8 + (lane & 3) * 2;
                const float* x0 = aux + (ll)b0 * 512 + gn;
                const float* u0 = uv  + (ll)b0 * 512 + gn;
                const float* x1 = aux + (ll)b1 * 512 + gn;
                const float* u1 = uv  + (ll)b1 * 512 + gn;
                p0 += fmaxf(acc[tm][tn][0] + x0[0], 0.f) * u0[0]
                    + fmaxf(acc[tm][tn][1] + x0[1], 0.f) * u0[1];
                p1 += fmaxf(acc[tm][tn][2] + x1[0], 0.f) * u1[0]
                    + fmaxf(acc[tm][tn][3] + x1[1], 0.f) * u1[1];
            }
            p0 += __shfl_xor_sync(0xffffffffu, p0, 1);
            p0 += __shfl_xor_sync(0xffffffffu, p0, 2);
            p1 += __shfl_xor_sync(0xffffffffu, p1, 1);
            p1 += __shfl_xor_sync(0xffffffffu, p1, 2);
            if ((lane & 3) == 0) {
                atomicAdd(&rowsum[lr0], p0);
                atomicAdd(&rowsum[lr0 + 8], p1);
            }
        }
    }
    if (MODE == 2) {
        __syncthreads();
        if (tid < 128) atomicAdd(&logit[m0 + tid], rowsum[tid]);
    }
}

// ===================== transposes & split producers ========================
__global__ __launch_bounds__(256)
void transpose_k(const float* __restrict__ know, __half* __restrict__ kh,
                 __half* __restrict__ kl)
{
    __shared__ float t[32][33];
    const int b = blockIdx.z;
    const int n0 = blockIdx.x * 32, d0 = blockIdx.y * 32;
    const int tx = threadIdx.x, ty = threadIdx.y;
#pragma unroll
    for (int r = 0; r < 32; r += 8) {
        int d = d0 + ty + r, n = n0 + tx;
        float v = 0.f;
        if (n < NHW) v = know[((ll)b * ND + d) * NHW + n];
        t[ty + r][tx] = v;
    }
    __syncthreads();
#pragma unroll
    for (int r = 0; r < 32; r += 8) {
        int n = n0 + ty + r, d = d0 + tx;
        if (n < NHW) splitw_t(kh, kl, b * NHW + n, d, 16, t[tx][ty + r]);
    }
}

struct TDesc { const float* src; __half* dh; ll E; int R; int kc; };
struct TBatch { TDesc d[9]; };

// dst tiled plane [n, k] = src[k, n]; src [R,512] row-major.
__global__ __launch_bounds__(256)
void trans_w(TBatch tb)
{
    const TDesc td = tb.d[blockIdx.z];
    const int k0 = blockIdx.y * 32, n0 = blockIdx.x * 32;
    if (k0 >= td.R) return;
    __half* dl = td.dh + td.E;
    __shared__ float t[32][33];
    const int tx = threadIdx.x, ty = threadIdx.y;
#pragma unroll
    for (int r = 0; r < 32; r += 8)
        t[ty + r][tx] = td.src[(ll)(k0 + ty + r) * 512 + n0 + tx];
    __syncthreads();
#pragma unroll
    for (int r = 0; r < 32; r += 8)
        splitw_t(td.dh, dl, n0 + ty + r, k0 + tx, td.kc, t[tx][ty + r]);
}

__global__ void wsumT_kernel(const float* __restrict__ Wwcat,
                             __half* __restrict__ nh)
{
    int i = blockIdx.x * 256 + threadIdx.x;
    int k = i & 511, n = i >> 9;
    float v = Wwcat[(ll)(512 + k) * 512 + n] + Wwcat[(ll)(1024 + k) * 512 + n];
    splitw_t(nh, nh + 524288, n, 512 + k, 32, v);
}

__global__ void b2init_kernel(const float* __restrict__ bc1, float* __restrict__ b2)
{
    int d = blockIdx.x * 256 + threadIdx.x;
    b2[d] = bc1[d];
}

// b2 += bk @ Wc1[D:2D], e-split across blockIdx.y
__global__ void bias2_kernel(const float* __restrict__ Wc1, const float* __restrict__ bk,
                             float* __restrict__ b2)
{
    int d = blockIdx.x * 256 + threadIdx.x;
    int e0 = blockIdx.y * 32;
    float acc = 0.f;
#pragma unroll
    for (int e = 0; e < 32; e++)
        acc += bk[e0 + e] * Wc1[(ll)(512 + e0 + e) * 512 + d];
    atomicAdd(&b2[d], acc);
}

// split copies: question | control0 | memory0 | Wc2 | Wk(original)
__global__ void copy_split(const float* __restrict__ q, const float* __restrict__ c0,
                           const float* __restrict__ m0, const float* __restrict__ wc2,
                           const float* __restrict__ wk,
                           char* __restrict__ Sb)
{
    int i = blockIdx.x * 256 + threadIdx.x;
    if (i < 262144) {
        __half* h = (__half*)(Sb + B_QR);
        splitw_t(h, h + 262144, i >> 10, i & 1023, 32, q[i]);
    } else if (i < 393216) {
        int j = i - 262144;
        __half* h = (__half*)(Sb + B_C0R);
        splitw_t(h, h + 131072, j >> 9, j & 511, 16, c0[j]);
    } else if (i < 524288) {
        int j = i - 393216;
        __half* h = (__half*)(Sb + B_M0R);
        splitw_t(h, h + 131072, j >> 9, j & 511, 16, m0[j]);
    } else if (i < 786432) {
        int j = i - 524288;
        __half* h = (__half*)(Sb + B_WC2R);
        splitw_t(h, h + 262144, j >> 9, j & 511, 16, wc2[j]);
    } else {
        int j = i - 786432;
        __half* h = (__half*)(Sb + B_WKP);
        splitw_t(h, h + 262144, j >> 9, j & 511, 16, wk[j]);
    }
}

__global__ void logit_init_kernel(const float* __restrict__ c, float* __restrict__ logit)
{
    int i = blockIdx.x * 256 + threadIdx.x;
    logit[i] = c[i / NHW];
}

// ===================== attention / reductions ==============================
__global__ __launch_bounds__(256)
void attnc_kernel(const float* __restrict__ words, const float* __restrict__ cq,
                  const float* __restrict__ wac, const float* __restrict__ bac,
                  float* __restrict__ control)
{
    const int b = blockIdx.x, tid = threadIdx.x;
    const int warp = tid >> 5, lane = tid & 31;
    __shared__ float cw[ND];
    __shared__ float sa[NS];
    for (int d = tid; d < ND; d += 256) cw[d] = cq[(ll)b * ND + d] * wac[d];
    __syncthreads();
#pragma unroll
    for (int r = 0; r < 4; r++) {
        int s = warp * 4 + r;
        const float* wp = words + ((ll)b * NS + s) * ND;
        float acc = 0.f;
        for (int d = lane; d < ND; d += 32) acc += cw[d] * wp[d];
#pragma unroll
        for (int o = 16; o; o >>= 1) acc += __shfl_xor_sync(0xffffffffu, acc, o);
        if (lane == 0) sa[s] = acc + bac[0];
    }
    __syncthreads();
    if (warp == 0) {
        float v = sa[lane], mx = v;
#pragma unroll
        for (int o = 16; o; o >>= 1) mx = fmaxf(mx, __shfl_xor_sync(0xffffffffu, mx, o));
        float e = expf(v - mx), sm = e;
#pragma unroll
        for (int o = 16; o; o >>= 1) sm += __shfl_xor_sync(0xffffffffu, sm, o);
        sa[lane] = e / sm;
    }
    __syncthreads();
    for (int d = tid; d < ND; d += 256) {
        float acc = 0.f;
#pragma unroll 8
        for (int s = 0; s < NS; s++) acc += sa[s] * words[((ll)b * NS + s) * ND + d];
        control[(ll)b * ND + d] = acc;
    }
}

__global__ __launch_bounds__(256)
void vc_kernel(const float* __restrict__ control, const float* __restrict__ war,
               const float* __restrict__ bc2, const float* __restrict__ bar,
               __half* __restrict__ vh, float* __restrict__ c)
{
    const int b = blockIdx.x, tid = threadIdx.x;
    __shared__ float s[256];
    float p = 0.f;
    for (int d = tid; d < ND; d += 256) {
        float vv = control[(ll)b * ND + d] * war[d];
        splitw_t(vh, vh + 131072, b, d, 16, vv);
        p += bc2[d] * vv;
    }
    s[tid] = p; __syncthreads();
    for (int o = 128; o; o >>= 1) { if (tid < o) s[tid] += s[tid + o]; __syncthreads(); }
    if (tid == 0) c[b] = s[0] + bar[0];
}

__global__ __launch_bounds__(256)
void softmaxn_kernel(const float* __restrict__ logit, float* __restrict__ ar)
{
    const int b = blockIdx.x, tid = threadIdx.x;
    __shared__ float s[256];
    float v = (tid < NHW) ? logit[(ll)b * NHW + tid] : -1e30f;
    s[tid] = v; __syncthreads();
    for (int o = 128; o; o >>= 1) { if (tid < o) s[tid] = fmaxf(s[tid], s[tid + o]); __syncthreads(); }
    float mx = s[0]; __syncthreads();
    float e = (tid < NHW) ? expf(v - mx) : 0.f;
    s[tid] = e; __syncthreads();
    for (int o = 128; o; o >>= 1) { if (tid < o) s[tid] += s[tid + o]; __syncthreads(); }
    float sum = s[0];
    if (tid < NHW) ar[(ll)b * NHW + tid] = e / sum;
}

__global__ __launch_bounds__(256)
void read_kernel(const float* __restrict__ know, const float* __restrict__ ar,
                 __half* __restrict__ rh)
{
    const int b = blockIdx.x, tid = threadIdx.x;
    const int warp = tid >> 5, lane = tid & 31;
    __shared__ float s[NHW];
    if (tid < NHW) s[tid] = ar[(ll)b * NHW + tid];
    __syncthreads();
    for (int d = warp; d < ND; d += 8) {
        const float* kp = know + ((ll)b * ND + d) * NHW;
        float acc = 0.f;
        for (int n = lane; n < NHW; n += 32) acc += kp[n] * s[n];
#pragma unroll
        for (int o = 16; o; o >>= 1) acc += __shfl_xor_sync(0xffffffffu, acc, o);
        if (lane == 0) splitw_t(rh, rh + 131072, b, d, 16, acc);
    }
}

// ===========================================================================
extern "C" void kernel_launch(void* const* d_in, const int* in_sizes, int n_in,
                              void* d_out, int out_size)
{
    const float* words    = (const float*)d_in[0];
    const float* question = (const float*)d_in[1];
    const float* know     = (const float*)d_in[2];
    const float* control0 = (const float*)d_in[3];
    const float* memory0  = (const float*)d_in[4];
    const float* Wsc  = (const float*)d_in[5];
    const float* bsc  = (const float*)d_in[6];
    const float* Wp   = (const float*)d_in[7];
    const float* bp   = (const float*)d_in[8];
    const float* Wcq  = (const float*)d_in[9];
    const float* bcq  = (const float*)d_in[10];
    const float* wac  = (const float*)d_in[11];
    const float* bac  = (const float*)d_in[12];
    const float* Wm   = (const float*)d_in[13];
    const float* bm   = (const float*)d_in[14];
    const float* Wk   = (const float*)d_in[15];
    const float* bk   = (const float*)d_in[16];
    const float* Wc1  = (const float*)d_in[17];
    const float* bc1  = (const float*)d_in[18];
    const float* Wc2  = (const float*)d_in[19];
    const float* bc2  = (const float*)d_in[20];
    const float* war  = (const float*)d_in[21];
    const float* bar  = (const float*)d_in[22];
    // d_in[23..26] dead: softmax over length-1 axis == 1 -> attn_mem == memory0
    const float* Wwcat = (const float*)d_in[27];
    const float* bwcat = (const float*)d_in[28];

    cudaFuncSetAttribute(tc_gemm<0>, cudaFuncAttributeMaxDynamicSharedMemorySize, SMB);
    cudaFuncSetAttribute(tc_gemm<1>, cudaFuncAttributeMaxDynamicSharedMemorySize, SMB);
    cudaFuncSetAttribute(tc_gemm<2>, cudaFuncAttributeMaxDynamicSharedMemorySize, SMB);

    char* Sb = nullptr;
    cudaGetSymbolAddress((void**)&Sb, g_s);

    float* outC = (float*)d_out;
    float* outM = (float*)d_out + (ll)NB * ND;

    auto F  = [&](ll off) { return (float*)(Sb + off); };
    auto Hh = [&](ll off) { return (__half*)(Sb + off); };
    auto OP = [&](ll off, ll E, int kc) -> Op {
        __half* h = (__half*)(Sb + off);
        return { h, h + E, kc };
    };
    Op Z = { nullptr, nullptr, 0 };

    // 1) weight transposes -> tiled split planes
    {
        TBatch tb;
        tb.d[0] = { Wk,                     Hh(B_WKT),   262144, 512, 16 };
        tb.d[1] = { Wc1,                    Hh(B_W1AT),  262144, 512, 16 };
        tb.d[2] = { Wc1 + (ll)ND * ND,      Hh(B_W1BT),  262144, 512, 16 };
        tb.d[3] = { Wsc,                    Hh(B_WSCT),  524288, 1024, 32 };
        tb.d[4] = { Wp,                     Hh(B_WPT),   262144, 512, 16 };
        tb.d[5] = { Wcq,                    Hh(B_WCQT),  524288, 1024, 32 };
        tb.d[6] = { Wm,                     Hh(B_WMT),   262144, 512, 16 };
        tb.d[7] = { Wc1 + (ll)2 * ND * ND,  Hh(B_WC1CT), 262144, 512, 16 };
        tb.d[8] = { Wwcat,                  Hh(B_NMBT),  524288, 512, 32 };
        trans_w<<<dim3(16, 32, 9), dim3(32, 8)>>>(tb);
    }
    // 2) knowT tiled split planes
    transpose_k<<<dim3(7, 16, NB), dim3(32, 8)>>>(know, Hh(B_KNOWT),
                                                  Hh(B_KNOWT) + 25690112);
    // 3) summed second half of next_mem B (chunks 16-31 of NMBT)
    wsumT_kernel<<<1024, 256>>>(Wwcat, Hh(B_NMBT));
    // 4) bias2 = bc1 + bk @ Wc1[D:2D]  (parallel e-split)
    b2init_kernel<<<2, 256>>>(bc1, F(B_BIAS2));
    bias2_kernel<<<dim3(2, 16), 256>>>(Wc1, bk, F(B_BIAS2));
    // 5) tiled split copies of direct operands
    copy_split<<<4096, 256>>>(question, control0, memory0, Wc2, Wk, Sb);

    // 6) q = tanh(question @ Wsc + bsc)  [K=1024] -> planes
    tc_gemm<0><<<dim3(4, 2), 512, SMB>>>(
        OP(B_QR, 262144, 32), Z, OP(B_WSCT, 524288, 32), Z, 1024,
        nullptr, Hh(B_Q), Hh(B_Q) + 131072, 512, 16, bsc, 1,
        nullptr, nullptr, nullptr);
    // 7) pm = memory0 @ Wm + bm -> fp32 + planes
    tc_gemm<0><<<dim3(4, 2), 512, SMB>>>(
        OP(B_M0R, 131072, 16), Z, OP(B_WMT, 262144, 16), Z, 512,
        F(B_PMF), Hh(B_PMP), Hh(B_PMP) + 131072, 512, 16, bm, 0,
        nullptr, nullptr, nullptr);
    // 8) HEAVY 1: spk = (knowT @ Wk + bk) * pm[b] -> planes
    tc_gemm<1><<<dim3(4, NM / 128), 512, SMB>>>(
        OP(B_KNOWT, 25690112, 16), Z, OP(B_WKT, 262144, 16), Z, 512,
        nullptr, Hh(B_SPK), Hh(B_SPK) + 25690112, 512, 16, bk, 0,
        F(B_PMF), nullptr, nullptr);
    // 9) WKWT[m,n] = sum_e W1bT[m,e] * Wk[n,e]  (Wk ORIGINAL orientation)
    tc_gemm<0><<<dim3(4, 4), 512, SMB>>>(
        OP(B_W1BT, 262144, 16), Z, OP(B_WKP, 262144, 16), Z, 512,
        nullptr, Hh(B_WKWT), Hh(B_WKWT) + 262144, 512, 16, nullptr, 0,
        nullptr, nullptr, nullptr);
    // 10) pa = q @ Wp + bp -> planes
    tc_gemm<0><<<dim3(4, 2), 512, SMB>>>(
        OP(B_Q, 131072, 16), Z, OP(B_WPT, 262144, 16), Z, 512,
        nullptr, Hh(B_PA), Hh(B_PA) + 131072, 512, 16, bp, 0,
        nullptr, nullptr, nullptr);
    // 11) cq = [control0 | pa] @ Wcq + bcq  [K=1024] -> fp32
    tc_gemm<0><<<dim3(4, 2), 512, SMB>>>(
        OP(B_C0R, 131072, 16), OP(B_PA, 131072, 16),
        OP(B_WCQT, 524288, 32), Z, 1024,
        F(B_CQ), nullptr, nullptr, 512, 16, bcq, 0,
        nullptr, nullptr, nullptr);
    // 12) control -> output
    attnc_kernel<<<NB, 256>>>(words, F(B_CQ), wac, bac, outC);
    // 13) v = control*war (planes); c = bc2.v + bar
    vc_kernel<<<NB, 256>>>(outC, war, bc2, bar, Hh(B_V), F(B_C));
    // 14) u = v @ Wc2 (BT[n,k] = Wc2[n,k]) -> fp32
    tc_gemm<0><<<dim3(4, 2), 512, SMB>>>(
        OP(B_V, 131072, 16), Z, OP(B_WC2R, 262144, 16), Z, 512,
        F(B_U), nullptr, nullptr, 512, 16, nullptr, 0,
        nullptr, nullptr, nullptr);
    // 15) pmc = pm @ Wc1[2D:3D] + bias2 -> fp32
    tc_gemm<0><<<dim3(4, 2), 512, SMB>>>(
        OP(B_PMP, 131072, 16), Z, OP(B_WC1CT, 262144, 16), Z, 512,
        F(B_PMC), nullptr, nullptr, 512, 16, F(B_BIAS2), 0,
        nullptr, nullptr, nullptr);
    // 16) logit init with c[b]
    logit_init_kernel<<<NM / 256, 256>>>(F(B_C), F(B_LOGIT));
    // 17) HEAVY 2: logit[m] += relu(spk@W1a + knowT@WkW1b + pmc[b]) . u[b]
    tc_gemm<2><<<dim3(4, NM / 128), 512, SMB>>>(
        OP(B_SPK, 25690112, 16), OP(B_KNOWT, 25690112, 16),
        OP(B_W1AT, 262144, 16), OP(B_WKWT, 262144, 16), 1024,
        nullptr, nullptr, nullptr, 512, 16, nullptr, 0,
        F(B_PMC), F(B_U), F(B_LOGIT));
    // 18-19) softmax over n, read (tiled planes)
    softmaxn_kernel<<<NB, 256>>>(F(B_LOGIT), F(B_AR));
    read_kernel<<<NB, 256>>>(know, F(B_AR), Hh(B_READ));
    // 20) next_mem = [read | memory0] @ nmBT^T + bwcat -> output fp32
    tc_gemm<0><<<dim3(4, 2), 512, SMB>>>(
        OP(B_READ, 131072, 16), OP(B_M0R, 131072, 16),
        OP(B_NMBT, 524288, 32), Z, 1024,
        outM, nullptr, nullptr, 512, 16, bwcat, 0,
        nullptr, nullptr, nullptr);
}

// round 8
// speedup vs baseline: 4.7541x; 1.1025x over previous
#include <cuda_runtime.h>
#include <cuda_fp16.h>
#include <cstdint>

typedef long long ll;

#define NB 256
#define NS 32
#define ND 512
#define NHW 196
#define NM (NB*NHW)   // 50176

// --------------------- scratch layout (BYTE offsets) ----------------------
// "planes" buffers hold E fp16 hi values then E fp16 lo values (4E bytes).
// GEMM-operand planes are TILED: [rowtile128][kchunk32][128r][64B],
// quad swizzle q' = q ^ ((r>>1)&3) inside each 64B row.
#define B_Q      ((ll)0)           // planes E=131072
#define B_PA     ((ll)524288)      // planes E=131072
#define B_CQ     ((ll)1048576)     // fp32 131072 (split-K accum)
#define B_PMP    ((ll)1572864)     // planes E=131072
#define B_PMF    ((ll)2097152)     // fp32 131072
#define B_PMC    ((ll)2621440)     // fp32 131072
#define B_V      ((ll)3145728)     // planes E=131072
#define B_U      ((ll)3670016)     // fp32 131072
#define B_READ   ((ll)4194304)     // planes E=131072
#define B_C      ((ll)4718592)     // fp32 256
#define B_BIAS2  ((ll)4719616)     // fp32 512
#define B_LOGIT  ((ll)4721664)     // fp32 50176
#define B_AR     ((ll)4922368)     // fp32 50176
#define B_WKT    ((ll)5242880)     // planes E=262144
#define B_W1AT   ((ll)6291456)     // planes E=262144
#define B_WKWT   ((ll)7340032)     // planes E=262144
#define B_WSCT   ((ll)8388608)     // planes E=524288 (rows512, K1024)
#define B_WPT    ((ll)10485760)    // planes E=262144
#define B_WCQT   ((ll)11534336)    // planes E=524288
#define B_WMT    ((ll)13631488)    // planes E=262144
#define B_WC1CT  ((ll)14680064)    // planes E=262144
#define B_NMBT   ((ll)15728640)    // planes E=524288 (rows512, K1024)
#define B_W1BT   ((ll)17825792)    // planes E=262144
#define B_QR     ((ll)18874368)    // planes E=262144 (question, K1024)
#define B_C0R    ((ll)19922944)    // planes E=131072
#define B_M0R    ((ll)20447232)    // planes E=131072
#define B_WC2R   ((ll)20971520)    // planes E=262144
#define B_KNOWT  ((ll)22020096)    // planes E=25690112
#define B_SPK    ((ll)124780544)   // planes E=25690112
#define B_WKP    ((ll)227540992)   // planes E=262144 (Wk original orientation)
#define B_QF     ((ll)228589568)   // fp32 131072 (q split-K accum)
#define B_TOTAL  ((ll)229113856)

__device__ __align__(1024) char g_s[B_TOTAL];

// ===================== arch-generic PTX helpers (sm_80/90 core) ============
__device__ __forceinline__ uint32_t smem_u32(const void* p) {
    uint32_t a;
    asm("{ .reg .u64 t; cvta.to.shared.u64 t, %1; cvt.u32.u64 %0, t; }"
        : "=r"(a) : "l"(p));
    return a;
}

#define MBARRIER_INIT(addr, cnt) \
    asm volatile("mbarrier.init.shared.b64 [%0], %1;" :: "r"(addr), "r"(cnt) : "memory")
#define MBARRIER_ARRIVE(addr) \
    asm volatile("mbarrier.arrive.shared.b64 _, [%0];" :: "r"(addr) : "memory")
#define MBARRIER_EXPECT_TX(addr, bytes) \
    asm volatile("mbarrier.arrive.expect_tx.shared.b64 _, [%0], %1;" \
                 :: "r"(addr), "r"(bytes) : "memory")
#define MBARRIER_WAIT_PARITY(addr, par) do { \
    uint32_t _m = (addr), _p = (par), _d; \
    asm volatile("{ .reg .pred p; mbarrier.try_wait.parity.acquire.cta.shared::cta.b64 p, [%1], %2;" \
                 " selp.b32 %0,1,0,p; }" : "=r"(_d) : "r"(_m), "r"(_p) : "memory"); \
    if (!_d) { \
        asm volatile("{ .reg .pred P1; WL_%=:" \
                     " mbarrier.try_wait.parity.acquire.cta.shared::cta.b64 P1, [%0], %1, 0x989680;" \
                     " @P1 bra.uni WD_%=; bra.uni WL_%=; WD_%=: }" \
                     :: "r"(_m), "r"(_p) : "memory"); \
    } \
} while (0)
#define FENCE_ASYNC() asm volatile("fence.proxy.async.shared::cta;" ::: "memory")

#define BULK_G2S(dst, src, bytes, mbar) \
    asm volatile("cp.async.bulk.shared::cluster.global.mbarrier::complete_tx::bytes " \
                 "[%0], [%1], %2, [%3];" \
                 :: "r"(dst), "l"(src), "r"(bytes), "r"(mbar) : "memory")

#define LDSM_X4(r0, r1, r2, r3, a) \
    asm volatile("ldmatrix.sync.aligned.m8n8.x4.shared.b16 {%0,%1,%2,%3}, [%4];" \
        : "=r"(r0), "=r"(r1), "=r"(r2), "=r"(r3) : "r"(a))

#define MMA16(d, a, b) \
    asm volatile("mma.sync.aligned.m16n8k16.row.col.f32.f16.f16.f32 " \
        "{%0,%1,%2,%3}, {%4,%5,%6,%7}, {%8,%9}, {%0,%1,%2,%3};" \
        : "+f"((d)[0]), "+f"((d)[1]), "+f"((d)[2]), "+f"((d)[3]) \
        : "r"((a)[0]), "r"((a)[1]), "r"((a)[2]), "r"((a)[3]), \
          "r"((b)[0]), "r"((b)[1]))

// element offset (in halves) inside a tiled-swizzled plane with kc chunks
__device__ __forceinline__ ll toff(int row, int k, int kc) {
    int r = row & 127;
    int quad = ((k >> 3) & 3) ^ ((r >> 1) & 3);
    return ((ll)((row >> 7) * kc + (k >> 5)) * 128 + r) * 32 + quad * 8 + (k & 7);
}

__device__ __forceinline__ void splitw_t(__half* hp, __half* lp, int row, int k,
                                         int kc, float v) {
    ll i = toff(row, k, kc);
    __half h = __float2half_rn(v);
    hp[i] = h;
    lp[i] = __float2half_rn(v - __half2float(h));
}
__device__ __forceinline__ void splitw2_t(__half* hp, __half* lp, int row, int k,
                                          int kc, float v0, float v1) {
    ll i = toff(row, k, kc);
    __half h0 = __float2half_rn(v0), h1 = __float2half_rn(v1);
    *(__half2*)(hp + i) = __halves2half2(h0, h1);
    *(__half2*)(lp + i) = __halves2half2(
        __float2half_rn(v0 - __half2float(h0)),
        __float2half_rn(v1 - __half2float(h1)));
}

struct Op { const __half* h; const __half* l; int kc; };

#define SMB 131712

// ===================== heavy GEMM (MODE1 / MODE2), unchanged ===============
template<int MODE>
__global__ __launch_bounds__(512, 1)
void tc_gemm(Op A1, Op A2, Op B1, Op B2, int K,
             __half* __restrict__ Ch, __half* __restrict__ Cl,
             int okc, const float* __restrict__ bias,
             const float* __restrict__ aux, const float* __restrict__ uv,
             float* __restrict__ logit)
{
    extern __shared__ char smem[];
    const uint32_t su = smem_u32(smem);
    const int tid = threadIdx.x;
    const int lane = tid & 31, wid = tid >> 5;
    const int wm = wid & 3, wn = wid >> 2;
    const int m0 = blockIdx.y * 128, n0 = blockIdx.x * 128;
    const int NC = K >> 5;
    const uint32_t mbF = su + 131072u, mbE = su + 131104u;

    if (tid == 0) {
#pragma unroll
        for (int s = 0; s < 4; s++) {
            MBARRIER_INIT(mbF + s * 8, 1);
            MBARRIER_INIT(mbE + s * 8, 16);
        }
        FENCE_ASYNC();
    }
    __syncthreads();

    auto issue = [&](int cn) {
        const bool a1 = cn < A1.kc, b1 = cn < B1.kc;
        const __half* ah = a1 ? A1.h : A2.h;
        const __half* al = a1 ? A1.l : A2.l;
        const __half* bh = b1 ? B1.h : B2.h;
        const __half* bl = b1 ? B1.l : B2.l;
        const int ca = a1 ? cn : cn - A1.kc;
        const int cb = b1 ? cn : cn - B1.kc;
        const int kca = a1 ? A1.kc : A2.kc;
        const int kcb = b1 ? B1.kc : B2.kc;
        const ll ao = ((ll)((m0 >> 7) * kca + ca)) * 8192;
        const ll bo = ((ll)((n0 >> 7) * kcb + cb)) * 8192;
        const uint32_t st = su + (uint32_t)(cn & 3) * 32768u;
        const uint32_t mb = mbF + (cn & 3) * 8;
        MBARRIER_EXPECT_TX(mb, 32768u);
        BULK_G2S(st,           (const char*)ah + ao, 8192u, mb);
        BULK_G2S(st + 8192u,   (const char*)al + ao, 8192u, mb);
        BULK_G2S(st + 16384u,  (const char*)bh + bo, 8192u, mb);
        BULK_G2S(st + 24576u,  (const char*)bl + bo, 8192u, mb);
    };

    if (tid == 0) { issue(0); if (NC > 1) issue(1); if (NC > 2) issue(2); }

    int ba[2], sa2[2], bb[2], sb2[2];
#pragma unroll
    for (int tm = 0; tm < 2; tm++) {
        int r = wm * 32 + tm * 16 + (lane & 7) + ((lane >> 3) & 1) * 8;
        ba[tm] = r * 64; sa2[tm] = (r >> 1) & 3;
    }
#pragma unroll
    for (int tp = 0; tp < 2; tp++) {
        int r = wn * 32 + tp * 16 + (lane & 7) + (lane >> 4) * 8;
        bb[tp] = r * 64; sb2[tp] = (r >> 1) & 3;
    }
    const int qa = lane >> 4, qb = (lane >> 3) & 1;

    float acc[2][4][4];
#pragma unroll
    for (int i = 0; i < 2; i++)
#pragma unroll
        for (int j = 0; j < 4; j++)
#pragma unroll
            for (int r = 0; r < 4; r++) acc[i][j][r] = 0.f;

    for (int c = 0; c < NC; c++) {
        if (tid == 0 && c + 3 < NC) {
            const int cn = c + 3;
            if (cn >= 4)
                MBARRIER_WAIT_PARITY(mbE + (cn & 3) * 8, ((cn >> 2) - 1) & 1);
            issue(cn);
        }
        MBARRIER_WAIT_PARITY(mbF + (c & 3) * 8, (c >> 2) & 1);
        const uint32_t st = su + (uint32_t)(c & 3) * 32768u;
#pragma unroll
        for (int kk2 = 0; kk2 < 2; kk2++) {
            uint32_t ah[2][4], al[2][4], bh[4][2], bl[4][2];
#pragma unroll
            for (int tm = 0; tm < 2; tm++) {
                const uint32_t ad = st + ba[tm]
                    + (uint32_t)((((qa + kk2 * 2) ^ sa2[tm]) & 3) * 16);
                LDSM_X4(ah[tm][0], ah[tm][1], ah[tm][2], ah[tm][3], ad);
                LDSM_X4(al[tm][0], al[tm][1], al[tm][2], al[tm][3], ad + 8192u);
            }
#pragma unroll
            for (int tp = 0; tp < 2; tp++) {
                const uint32_t bd = st + 16384u + bb[tp]
                    + (uint32_t)((((qb + kk2 * 2) ^ sb2[tp]) & 3) * 16);
                uint32_t r0, r1, r2, r3;
                LDSM_X4(r0, r1, r2, r3, bd);
                bh[2*tp][0] = r0; bh[2*tp][1] = r1;
                bh[2*tp+1][0] = r2; bh[2*tp+1][1] = r3;
                LDSM_X4(r0, r1, r2, r3, bd + 8192u);
                bl[2*tp][0] = r0; bl[2*tp][1] = r1;
                bl[2*tp+1][0] = r2; bl[2*tp+1][1] = r3;
            }
#pragma unroll
            for (int tm = 0; tm < 2; tm++)
#pragma unroll
                for (int tn = 0; tn < 4; tn++) {
                    MMA16(acc[tm][tn], ah[tm], bh[tn]);
                    MMA16(acc[tm][tn], ah[tm], bl[tn]);
                    MMA16(acc[tm][tn], al[tm], bh[tn]);
                }
        }
        if (lane == 0) MBARRIER_ARRIVE(mbE + (c & 3) * 8);
    }

    float* rowsum = (float*)(smem + 131136);
    if (MODE == 2) {
        __syncthreads();
        if (tid < 128) rowsum[tid] = 0.f;
        __syncthreads();
    }

#pragma unroll
    for (int tm = 0; tm < 2; tm++) {
        const int lr0 = wm * 32 + tm * 16 + (lane >> 2);
        const int r0 = m0 + lr0, r1 = r0 + 8;
        if (MODE == 1) {
            const int b0 = r0 / NHW, b1 = r1 / NHW;
#pragma unroll
            for (int tn = 0; tn < 4; tn++) {
                const int gn = n0 + wn * 32 + tn * 8 + (lane & 3) * 2;
                const float bb0 = bias[gn], bb1 = bias[gn + 1];
                const float* a0 = aux + (ll)b0 * 512 + gn;
                const float* a1 = aux + (ll)b1 * 512 + gn;
                splitw2_t(Ch, Cl, r0, gn, okc,
                          (acc[tm][tn][0] + bb0) * a0[0],
                          (acc[tm][tn][1] + bb1) * a0[1]);
                splitw2_t(Ch, Cl, r1, gn, okc,
                          (acc[tm][tn][2] + bb0) * a1[0],
                          (acc[tm][tn][3] + bb1) * a1[1]);
            }
        } else {
            const int b0 = r0 / NHW, b1 = r1 / NHW;
            float p0 = 0.f, p1 = 0.f;
#pragma unroll
            for (int tn = 0; tn < 4; tn++) {
                const int gn = n0 + wn * 32 + tn * 8 + (lane & 3) * 2;
                const float* x0 = aux + (ll)b0 * 512 + gn;
                const float* u0 = uv  + (ll)b0 * 512 + gn;
                const float* x1 = aux + (ll)b1 * 512 + gn;
                const float* u1 = uv  + (ll)b1 * 512 + gn;
                p0 += fmaxf(acc[tm][tn][0] + x0[0], 0.f) * u0[0]
                    + fmaxf(acc[tm][tn][1] + x0[1], 0.f) * u0[1];
                p1 += fmaxf(acc[tm][tn][2] + x1[0], 0.f) * u1[0]
                    + fmaxf(acc[tm][tn][3] + x1[1], 0.f) * u1[1];
            }
            p0 += __shfl_xor_sync(0xffffffffu, p0, 1);
            p0 += __shfl_xor_sync(0xffffffffu, p0, 2);
            p1 += __shfl_xor_sync(0xffffffffu, p1, 1);
            p1 += __shfl_xor_sync(0xffffffffu, p1, 2);
            if ((lane & 3) == 0) {
                atomicAdd(&rowsum[lr0], p0);
                atomicAdd(&rowsum[lr0 + 8], p1);
            }
        }
    }
    if (MODE == 2) {
        __syncthreads();
        if (tid < 128) atomicAdd(&logit[m0 + tid], rowsum[tid]);
    }
}

// ============ batched small GEMM (MODE0 semantics, desc per blockIdx.z) ====
struct GD {
    const __half *ah, *al; int akc;
    const __half *bh, *bl; int bkc;
    int K;
    float* C; __half* Ch; __half* Cl; int okc;
    const float* bias; int act; int atomic; int my;
};
struct GDBatch { GD d[4]; };

__global__ __launch_bounds__(512, 1)
void tc_gemmb(GDBatch tb)
{
    const GD g = tb.d[blockIdx.z];
    if (blockIdx.y >= g.my) return;
    extern __shared__ char smem[];
    const uint32_t su = smem_u32(smem);
    const int tid = threadIdx.x;
    const int lane = tid & 31, wid = tid >> 5;
    const int wm = wid & 3, wn = wid >> 2;
    const int m0 = blockIdx.y * 128, n0 = blockIdx.x * 128;
    const int NC = g.K >> 5;
    const uint32_t mbF = su + 131072u, mbE = su + 131104u;

    if (tid == 0) {
#pragma unroll
        for (int s = 0; s < 4; s++) {
            MBARRIER_INIT(mbF + s * 8, 1);
            MBARRIER_INIT(mbE + s * 8, 16);
        }
        FENCE_ASYNC();
    }
    __syncthreads();

    auto issue = [&](int cn) {
        const ll ao = ((ll)((m0 >> 7) * g.akc + cn)) * 8192;
        const ll bo = ((ll)((n0 >> 7) * g.bkc + cn)) * 8192;
        const uint32_t st = su + (uint32_t)(cn & 3) * 32768u;
        const uint32_t mb = mbF + (cn & 3) * 8;
        MBARRIER_EXPECT_TX(mb, 32768u);
        BULK_G2S(st,           (const char*)g.ah + ao, 8192u, mb);
        BULK_G2S(st + 8192u,   (const char*)g.al + ao, 8192u, mb);
        BULK_G2S(st + 16384u,  (const char*)g.bh + bo, 8192u, mb);
        BULK_G2S(st + 24576u,  (const char*)g.bl + bo, 8192u, mb);
    };

    if (tid == 0) { issue(0); if (NC > 1) issue(1); if (NC > 2) issue(2); }

    int ba[2], sa2[2], bb[2], sb2[2];
#pragma unroll
    for (int tm = 0; tm < 2; tm++) {
        int r = wm * 32 + tm * 16 + (lane & 7) + ((lane >> 3) & 1) * 8;
        ba[tm] = r * 64; sa2[tm] = (r >> 1) & 3;
    }
#pragma unroll
    for (int tp = 0; tp < 2; tp++) {
        int r = wn * 32 + tp * 16 + (lane & 7) + (lane >> 4) * 8;
        bb[tp] = r * 64; sb2[tp] = (r >> 1) & 3;
    }
    const int qa = lane >> 4, qb = (lane >> 3) & 1;

    float acc[2][4][4];
#pragma unroll
    for (int i = 0; i < 2; i++)
#pragma unroll
        for (int j = 0; j < 4; j++)
#pragma unroll
            for (int r = 0; r < 4; r++) acc[i][j][r] = 0.f;

    for (int c = 0; c < NC; c++) {
        if (tid == 0 && c + 3 < NC) {
            const int cn = c + 3;
            if (cn >= 4)
                MBARRIER_WAIT_PARITY(mbE + (cn & 3) * 8, ((cn >> 2) - 1) & 1);
            issue(cn);
        }
        MBARRIER_WAIT_PARITY(mbF + (c & 3) * 8, (c >> 2) & 1);
        const uint32_t st = su + (uint32_t)(c & 3) * 32768u;
#pragma unroll
        for (int kk2 = 0; kk2 < 2; kk2++) {
            uint32_t ah[2][4], al[2][4], bh[4][2], bl[4][2];
#pragma unroll
            for (int tm = 0; tm < 2; tm++) {
                const uint32_t ad = st + ba[tm]
                    + (uint32_t)((((qa + kk2 * 2) ^ sa2[tm]) & 3) * 16);
                LDSM_X4(ah[tm][0], ah[tm][1], ah[tm][2], ah[tm][3], ad);
                LDSM_X4(al[tm][0], al[tm][1], al[tm][2], al[tm][3], ad + 8192u);
            }
#pragma unroll
            for (int tp = 0; tp < 2; tp++) {
                const uint32_t bd = st + 16384u + bb[tp]
                    + (uint32_t)((((qb + kk2 * 2) ^ sb2[tp]) & 3) * 16);
                uint32_t r0, r1, r2, r3;
                LDSM_X4(r0, r1, r2, r3, bd);
                bh[2*tp][0] = r0; bh[2*tp][1] = r1;
                bh[2*tp+1][0] = r2; bh[2*tp+1][1] = r3;
                LDSM_X4(r0, r1, r2, r3, bd + 8192u);
                bl[2*tp][0] = r0; bl[2*tp][1] = r1;
                bl[2*tp+1][0] = r2; bl[2*tp+1][1] = r3;
            }
#pragma unroll
            for (int tm = 0; tm < 2; tm++)
#pragma unroll
                for (int tn = 0; tn < 4; tn++) {
                    MMA16(acc[tm][tn], ah[tm], bh[tn]);
                    MMA16(acc[tm][tn], ah[tm], bl[tn]);
                    MMA16(acc[tm][tn], al[tm], bh[tn]);
                }
        }
        if (lane == 0) MBARRIER_ARRIVE(mbE + (c & 3) * 8);
    }

#pragma unroll
    for (int tm = 0; tm < 2; tm++) {
        const int lr0 = wm * 32 + tm * 16 + (lane >> 2);
        const int r0 = m0 + lr0, r1 = r0 + 8;
#pragma unroll
        for (int tn = 0; tn < 4; tn++) {
            const int gn = n0 + wn * 32 + tn * 8 + (lane & 3) * 2;
            float v0 = acc[tm][tn][0], v1 = acc[tm][tn][1];
            float v2 = acc[tm][tn][2], v3 = acc[tm][tn][3];
            if (g.bias) {
                float b0 = g.bias[gn], b1 = g.bias[gn + 1];
                v0 += b0; v1 += b1; v2 += b0; v3 += b1;
            }
            if (g.act == 1) {
                v0 = tanhf(v0); v1 = tanhf(v1);
                v2 = tanhf(v2); v3 = tanhf(v3);
            }
            if (g.atomic) {
                atomicAdd(&g.C[(ll)r0 * 512 + gn], v0);
                atomicAdd(&g.C[(ll)r0 * 512 + gn + 1], v1);
                atomicAdd(&g.C[(ll)r1 * 512 + gn], v2);
                atomicAdd(&g.C[(ll)r1 * 512 + gn + 1], v3);
            } else {
                if (g.C) {
                    *(float2*)&g.C[(ll)r0 * 512 + gn] = make_float2(v0, v1);
                    *(float2*)&g.C[(ll)r1 * 512 + gn] = make_float2(v2, v3);
                }
                if (g.Ch) {
                    splitw2_t(g.Ch, g.Cl, r0, gn, g.okc, v0, v1);
                    splitw2_t(g.Ch, g.Cl, r1, gn, g.okc, v2, v3);
                }
            }
        }
    }
}

// ===================== transposes & split producers ========================
__global__ __launch_bounds__(256)
void transpose_k(const float* __restrict__ know, __half* __restrict__ kh,
                 __half* __restrict__ kl)
{
    __shared__ float t[32][33];
    const int b = blockIdx.z;
    const int n0 = blockIdx.x * 32, d0 = blockIdx.y * 32;
    const int tx = threadIdx.x, ty = threadIdx.y;
#pragma unroll
    for (int r = 0; r < 32; r += 8) {
        int d = d0 + ty + r, n = n0 + tx;
        float v = 0.f;
        if (n < NHW) v = know[((ll)b * ND + d) * NHW + n];
        t[ty + r][tx] = v;
    }
    __syncthreads();
#pragma unroll
    for (int r = 0; r < 32; r += 8) {
        int n = n0 + ty + r, d = d0 + tx;
        if (n < NHW) splitw_t(kh, kl, b * NHW + n, d, 16, t[tx][ty + r]);
    }
}

struct TDesc { const float* src; __half* dh; ll E; int R; int kc; };
struct TBatch { TDesc d[9]; };

__global__ __launch_bounds__(256)
void trans_w(TBatch tb)
{
    const TDesc td = tb.d[blockIdx.z];
    const int k0 = blockIdx.y * 32, n0 = blockIdx.x * 32;
    if (k0 >= td.R) return;
    __half* dl = td.dh + td.E;
    __shared__ float t[32][33];
    const int tx = threadIdx.x, ty = threadIdx.y;
#pragma unroll
    for (int r = 0; r < 32; r += 8)
        t[ty + r][tx] = td.src[(ll)(k0 + ty + r) * 512 + n0 + tx];
    __syncthreads();
#pragma unroll
    for (int r = 0; r < 32; r += 8)
        splitw_t(td.dh, dl, n0 + ty + r, k0 + tx, td.kc, t[tx][ty + r]);
}

__global__ void wsumT_kernel(const float* __restrict__ Wwcat,
                             __half* __restrict__ nh)
{
    int i = blockIdx.x * 256 + threadIdx.x;
    int k = i & 511, n = i >> 9;
    float v = Wwcat[(ll)(512 + k) * 512 + n] + Wwcat[(ll)(1024 + k) * 512 + n];
    splitw_t(nh, nh + 524288, n, 512 + k, 32, v);
}

__global__ void b2init_kernel(const float* __restrict__ bc1, float* __restrict__ b2)
{
    int d = blockIdx.x * 256 + threadIdx.x;
    b2[d] = bc1[d];
}

__global__ void bias2_kernel(const float* __restrict__ Wc1, const float* __restrict__ bk,
                             float* __restrict__ b2)
{
    int d = blockIdx.x * 256 + threadIdx.x;
    int e0 = blockIdx.y * 32;
    float acc = 0.f;
#pragma unroll
    for (int e = 0; e < 32; e++)
        acc += bk[e0 + e] * Wc1[(ll)(512 + e0 + e) * 512 + d];
    atomicAdd(&b2[d], acc);
}

// zero split-K accumulators; outM pre-filled with bwcat broadcast
__global__ void init_bufs(const float* __restrict__ bwcat,
                          char* __restrict__ Sb, float* __restrict__ outM)
{
    int i = blockIdx.x * 256 + threadIdx.x;
    ((float*)(Sb + B_QF))[i] = 0.f;
    ((float*)(Sb + B_CQ))[i] = 0.f;
    outM[i] = bwcat[i & 511];
}

// q planes = split(tanh(qf + bsc))
__global__ void tanhsplit_kernel(const float* __restrict__ qf,
                                 const float* __restrict__ bsc,
                                 __half* __restrict__ qh)
{
    int i = blockIdx.x * 256 + threadIdx.x;
    float v = tanhf(qf[i] + bsc[i & 511]);
    splitw_t(qh, qh + 131072, i >> 9, i & 511, 16, v);
}

__global__ void copy_split(const float* __restrict__ q, const float* __restrict__ c0,
                           const float* __restrict__ m0, const float* __restrict__ wc2,
                           const float* __restrict__ wk,
                           char* __restrict__ Sb)
{
    int i = blockIdx.x * 256 + threadIdx.x;
    if (i < 262144) {
        __half* h = (__half*)(Sb + B_QR);
        splitw_t(h, h + 262144, i >> 10, i & 1023, 32, q[i]);
    } else if (i < 393216) {
        int j = i - 262144;
        __half* h = (__half*)(Sb + B_C0R);
        splitw_t(h, h + 131072, j >> 9, j & 511, 16, c0[j]);
    } else if (i < 524288) {
        int j = i - 393216;
        __half* h = (__half*)(Sb + B_M0R);
        splitw_t(h, h + 131072, j >> 9, j & 511, 16, m0[j]);
    } else if (i < 786432) {
        int j = i - 524288;
        __half* h = (__half*)(Sb + B_WC2R);
        splitw_t(h, h + 262144, j >> 9, j & 511, 16, wc2[j]);
    } else {
        int j = i - 786432;
        __half* h = (__half*)(Sb + B_WKP);
        splitw_t(h, h + 262144, j >> 9, j & 511, 16, wk[j]);
    }
}

__global__ void logit_init_kernel(const float* __restrict__ c, float* __restrict__ logit)
{
    int i = blockIdx.x * 256 + threadIdx.x;
    logit[i] = c[i / NHW];
}

// ===================== attention / reductions ==============================
__global__ __launch_bounds__(256)
void attnc_kernel(const float* __restrict__ words, const float* __restrict__ cq,
                  const float* __restrict__ bcq,
                  const float* __restrict__ wac, const float* __restrict__ bac,
                  float* __restrict__ control)
{
    const int b = blockIdx.x, tid = threadIdx.x;
    const int warp = tid >> 5, lane = tid & 31;
    __shared__ float cw[ND];
    __shared__ float sa[NS];
    for (int d = tid; d < ND; d += 256)
        cw[d] = (cq[(ll)b * ND + d] + bcq[d]) * wac[d];
    __syncthreads();
#pragma unroll
    for (int r = 0; r < 4; r++) {
        int s = warp * 4 + r;
        const float* wp = words + ((ll)b * NS + s) * ND;
        float acc = 0.f;
        for (int d = lane; d < ND; d += 32) acc += cw[d] * wp[d];
#pragma unroll
        for (int o = 16; o; o >>= 1) acc += __shfl_xor_sync(0xffffffffu, acc, o);
        if (lane == 0) sa[s] = acc + bac[0];
    }
    __syncthreads();
    if (warp == 0) {
        float v = sa[lane], mx = v;
#pragma unroll
        for (int o = 16; o; o >>= 1) mx = fmaxf(mx, __shfl_xor_sync(0xffffffffu, mx, o));
        float e = expf(v - mx), sm = e;
#pragma unroll
        for (int o = 16; o; o >>= 1) sm += __shfl_xor_sync(0xffffffffu, sm, o);
        sa[lane] = e / sm;
    }
    __syncthreads();
    for (int d = tid; d < ND; d += 256) {
        float acc = 0.f;
#pragma unroll 8
        for (int s = 0; s < NS; s++) acc += sa[s] * words[((ll)b * NS + s) * ND + d];
        control[(ll)b * ND + d] = acc;
    }
}

__global__ __launch_bounds__(256)
void vc_kernel(const float* __restrict__ control, const float* __restrict__ war,
               const float* __restrict__ bc2, const float* __restrict__ bar,
               __half* __restrict__ vh, float* __restrict__ c)
{
    const int b = blockIdx.x, tid = threadIdx.x;
    __shared__ float s[256];
    float p = 0.f;
    for (int d = tid; d < ND; d += 256) {
        float vv = control[(ll)b * ND + d] * war[d];
        splitw_t(vh, vh + 131072, b, d, 16, vv);
        p += bc2[d] * vv;
    }
    s[tid] = p; __syncthreads();
    for (int o = 128; o; o >>= 1) { if (tid < o) s[tid] += s[tid + o]; __syncthreads(); }
    if (tid == 0) c[b] = s[0] + bar[0];
}

__global__ __launch_bounds__(256)
void softmaxn_kernel(const float* __restrict__ logit, float* __restrict__ ar)
{
    const int b = blockIdx.x, tid = threadIdx.x;
    __shared__ float s[256];
    float v = (tid < NHW) ? logit[(ll)b * NHW + tid] : -1e30f;
    s[tid] = v; __syncthreads();
    for (int o = 128; o; o >>= 1) { if (tid < o) s[tid] = fmaxf(s[tid], s[tid + o]); __syncthreads(); }
    float mx = s[0]; __syncthreads();
    float e = (tid < NHW) ? expf(v - mx) : 0.f;
    s[tid] = e; __syncthreads();
    for (int o = 128; o; o >>= 1) { if (tid < o) s[tid] += s[tid + o]; __syncthreads(); }
    float sum = s[0];
    if (tid < NHW) ar[(ll)b * NHW + tid] = e / sum;
}

__global__ __launch_bounds__(256)
void read_kernel(const float* __restrict__ know, const float* __restrict__ ar,
                 __half* __restrict__ rh)
{
    const int b = blockIdx.x, tid = threadIdx.x;
    const int warp = tid >> 5, lane = tid & 31;
    __shared__ float s[NHW];
    if (tid < NHW) s[tid] = ar[(ll)b * NHW + tid];
    __syncthreads();
    for (int d = warp; d < ND; d += 8) {
        const float* kp = know + ((ll)b * ND + d) * NHW;
        float acc = 0.f;
        for (int n = lane; n < NHW; n += 32) acc += kp[n] * s[n];
#pragma unroll
        for (int o = 16; o; o >>= 1) acc += __shfl_xor_sync(0xffffffffu, acc, o);
        if (lane == 0) splitw_t(rh, rh + 131072, b, d, 16, acc);
    }
}

// ===========================================================================
extern "C" void kernel_launch(void* const* d_in, const int* in_sizes, int n_in,
                              void* d_out, int out_size)
{
    const float* words    = (const float*)d_in[0];
    const float* question = (const float*)d_in[1];
    const float* know     = (const float*)d_in[2];
    const float* control0 = (const float*)d_in[3];
    const float* memory0  = (const float*)d_in[4];
    const float* Wsc  = (const float*)d_in[5];
    const float* bsc  = (const float*)d_in[6];
    const float* Wp   = (const float*)d_in[7];
    const float* bp   = (const float*)d_in[8];
    const float* Wcq  = (const float*)d_in[9];
    const float* bcq  = (const float*)d_in[10];
    const float* wac  = (const float*)d_in[11];
    const float* bac  = (const float*)d_in[12];
    const float* Wm   = (const float*)d_in[13];
    const float* bm   = (const float*)d_in[14];
    const float* Wk   = (const float*)d_in[15];
    const float* bk   = (const float*)d_in[16];
    const float* Wc1  = (const float*)d_in[17];
    const float* bc1  = (const float*)d_in[18];
    const float* Wc2  = (const float*)d_in[19];
    const float* bc2  = (const float*)d_in[20];
    const float* war  = (const float*)d_in[21];
    const float* bar  = (const float*)d_in[22];
    // d_in[23..26] dead: softmax over length-1 axis == 1 -> attn_mem == memory0
    const float* Wwcat = (const float*)d_in[27];
    const float* bwcat = (const float*)d_in[28];

    cudaFuncSetAttribute(tc_gemm<1>, cudaFuncAttributeMaxDynamicSharedMemorySize, SMB);
    cudaFuncSetAttribute(tc_gemm<2>, cudaFuncAttributeMaxDynamicSharedMemorySize, SMB);
    cudaFuncSetAttribute(tc_gemmb, cudaFuncAttributeMaxDynamicSharedMemorySize, SMB);

    char* Sb = nullptr;
    cudaGetSymbolAddress((void**)&Sb, g_s);

    float* outC = (float*)d_out;
    float* outM = (float*)d_out + (ll)NB * ND;

    auto F  = [&](ll off) { return (float*)(Sb + off); };
    auto Hh = [&](ll off) { return (__half*)(Sb + off); };
    auto OP = [&](ll off, ll E, int kc) -> Op {
        __half* h = (__half*)(Sb + off);
        return { h, h + E, kc };
    };
    Op Z = { nullptr, nullptr, 0 };

    // ---------- prep (independent, wide) ----------
    init_bufs<<<512, 256>>>(bwcat, Sb, outM);
    {
        TBatch tb;
        tb.d[0] = { Wk,                     Hh(B_WKT),   262144, 512, 16 };
        tb.d[1] = { Wc1,                    Hh(B_W1AT),  262144, 512, 16 };
        tb.d[2] = { Wc1 + (ll)ND * ND,      Hh(B_W1BT),  262144, 512, 16 };
        tb.d[3] = { Wsc,                    Hh(B_WSCT),  524288, 1024, 32 };
        tb.d[4] = { Wp,                     Hh(B_WPT),   262144, 512, 16 };
        tb.d[5] = { Wcq,                    Hh(B_WCQT),  524288, 1024, 32 };
        tb.d[6] = { Wm,                     Hh(B_WMT),   262144, 512, 16 };
        tb.d[7] = { Wc1 + (ll)2 * ND * ND,  Hh(B_WC1CT), 262144, 512, 16 };
        tb.d[8] = { Wwcat,                  Hh(B_NMBT),  524288, 512, 32 };
        trans_w<<<dim3(16, 32, 9), dim3(32, 8)>>>(tb);
    }
    transpose_k<<<dim3(7, 16, NB), dim3(32, 8)>>>(know, Hh(B_KNOWT),
                                                  Hh(B_KNOWT) + 25690112);
    wsumT_kernel<<<1024, 256>>>(Wwcat, Hh(B_NMBT));
    b2init_kernel<<<2, 256>>>(bc1, F(B_BIAS2));
    bias2_kernel<<<dim3(2, 16), 256>>>(Wc1, bk, F(B_BIAS2));
    copy_split<<<4096, 256>>>(question, control0, memory0, Wc2, Wk, Sb);

    const ll CH16 = 16 * 4096;   // +16 chunks (halves) within a K=1024 layout

    // ---------- batch1: q-half1, q-half2 (split-K atomic), pm, WkW1b ------
    {
        GDBatch b{};
        b.d[0] = { Hh(B_QR), Hh(B_QR) + 262144, 32,
                   Hh(B_WSCT), Hh(B_WSCT) + 524288, 32,
                   512, F(B_QF), nullptr, nullptr, 0, nullptr, 0, 1, 2 };
        b.d[1] = { Hh(B_QR) + CH16, Hh(B_QR) + 262144 + CH16, 32,
                   Hh(B_WSCT) + CH16, Hh(B_WSCT) + 524288 + CH16, 32,
                   512, F(B_QF), nullptr, nullptr, 0, nullptr, 0, 1, 2 };
        b.d[2] = { Hh(B_M0R), Hh(B_M0R) + 131072, 16,
                   Hh(B_WMT), Hh(B_WMT) + 262144, 16,
                   512, F(B_PMF), Hh(B_PMP), Hh(B_PMP) + 131072, 16, bm, 0, 0, 2 };
        b.d[3] = { Hh(B_W1BT), Hh(B_W1BT) + 262144, 16,
                   Hh(B_WKP), Hh(B_WKP) + 262144, 16,
                   512, nullptr, Hh(B_WKWT), Hh(B_WKWT) + 262144, 16,
                   nullptr, 0, 0, 4 };
        tc_gemmb<<<dim3(4, 4, 4), 512, SMB>>>(b);
    }
    // q planes = split(tanh(qf + bsc))
    tanhsplit_kernel<<<512, 256>>>(F(B_QF), bsc, Hh(B_Q));

    // ---------- HEAVY 1: spk = (knowT @ Wk + bk) * pm[b] -> planes --------
    tc_gemm<1><<<dim3(4, NM / 128), 512, SMB>>>(
        OP(B_KNOWT, 25690112, 16), Z, OP(B_WKT, 262144, 16), Z, 512,
        Hh(B_SPK), Hh(B_SPK) + 25690112, 16, bk,
        F(B_PMF), nullptr, nullptr);

    // ---------- batch2: pa, pmc ----------
    {
        GDBatch b{};
        b.d[0] = { Hh(B_Q), Hh(B_Q) + 131072, 16,
                   Hh(B_WPT), Hh(B_WPT) + 262144, 16,
                   512, nullptr, Hh(B_PA), Hh(B_PA) + 131072, 16, bp, 0, 0, 2 };
        b.d[1] = { Hh(B_PMP), Hh(B_PMP) + 131072, 16,
                   Hh(B_WC1CT), Hh(B_WC1CT) + 262144, 16,
                   512, F(B_PMC), nullptr, nullptr, 0, F(B_BIAS2), 0, 0, 2 };
        tc_gemmb<<<dim3(4, 2, 2), 512, SMB>>>(b);
    }
    // ---------- cq split-K batch (atomic into zeroed B_CQ) ----------
    {
        GDBatch b{};
        b.d[0] = { Hh(B_C0R), Hh(B_C0R) + 131072, 16,
                   Hh(B_WCQT), Hh(B_WCQT) + 524288, 32,
                   512, F(B_CQ), nullptr, nullptr, 0, nullptr, 0, 1, 2 };
        b.d[1] = { Hh(B_PA), Hh(B_PA) + 131072, 16,
                   Hh(B_WCQT) + CH16, Hh(B_WCQT) + 524288 + CH16, 32,
                   512, F(B_CQ), nullptr, nullptr, 0, nullptr, 0, 1, 2 };
        tc_gemmb<<<dim3(4, 2, 2), 512, SMB>>>(b);
    }
    // control -> output (bcq folded in)
    attnc_kernel<<<NB, 256>>>(words, F(B_CQ), bcq, wac, bac, outC);
    vc_kernel<<<NB, 256>>>(outC, war, bc2, bar, Hh(B_V), F(B_C));
    logit_init_kernel<<<NM / 256, 256>>>(F(B_C), F(B_LOGIT));
    // u = v @ Wc2
    {
        GDBatch b{};
        b.d[0] = { Hh(B_V), Hh(B_V) + 131072, 16,
                   Hh(B_WC2R), Hh(B_WC2R) + 262144, 16,
                   512, F(B_U), nullptr, nullptr, 0, nullptr, 0, 0, 2 };
        tc_gemmb<<<dim3(4, 2, 1), 512, SMB>>>(b);
    }
    // ---------- HEAVY 2 ----------
    tc_gemm<2><<<dim3(4, NM / 128), 512, SMB>>>(
        OP(B_SPK, 25690112, 16), OP(B_KNOWT, 25690112, 16),
        OP(B_W1AT, 262144, 16), OP(B_WKWT, 262144, 16), 1024,
        nullptr, nullptr, 16, nullptr,
        F(B_PMC), F(B_U), F(B_LOGIT));

    softmaxn_kernel<<<NB, 256>>>(F(B_LOGIT), F(B_AR));
    read_kernel<<<NB, 256>>>(know, F(B_AR), Hh(B_READ));

    // ---------- next_mem split-K batch (atomic into bwcat-filled outM) ----
    {
        GDBatch b{};
        b.d[0] = { Hh(B_READ), Hh(B_READ) + 131072, 16,
                   Hh(B_NMBT), Hh(B_NMBT) + 524288, 32,
                   512, outM, nullptr, nullptr, 0, nullptr, 0, 1, 2 };
        b.d[1] = { Hh(B_M0R), Hh(B_M0R) + 131072, 16,
                   Hh(B_NMBT) + CH16, Hh(B_NMBT) + 524288 + CH16, 32,
                   512, outM, nullptr, nullptr, 0, nullptr, 0, 1, 2 };
        tc_gemmb<<<dim3(4, 2, 2), 512, SMB>>>(b);
    }
}

// round 9
// speedup vs baseline: 4.8779x; 1.0260x over previous
#include <cuda_runtime.h>
#include <cuda_fp16.h>
#include <cstdint>

typedef long long ll;

#define NB 256
#define NS 32
#define ND 512
#define NHW 196
#define NM (NB*NHW)   // 50176

// --------------------- scratch layout (BYTE offsets) ----------------------
// "planes" buffers hold E fp16 hi values then E fp16 lo values (4E bytes).
// GEMM-operand planes are TILED: [rowtile128][kchunk32][128r][64B],
// quad swizzle q' = q ^ ((r>>1)&3) inside each 64B row.
#define B_Q      ((ll)0)           // planes E=131072
#define B_PA     ((ll)524288)      // planes E=131072
#define B_CQ     ((ll)1048576)     // fp32 131072 (split-K accum)
#define B_PMP    ((ll)1572864)     // planes E=131072
#define B_PMF    ((ll)2097152)     // fp32 131072
#define B_PMC    ((ll)2621440)     // fp32 131072
#define B_V      ((ll)3145728)     // planes E=131072
#define B_U      ((ll)3670016)     // fp32 131072
#define B_READ   ((ll)4194304)     // planes E=131072
#define B_BIAS2  ((ll)4719616)     // fp32 512
#define B_LOGIT  ((ll)4721664)     // fp32 50176
#define B_AR     ((ll)4922368)     // fp32 50176
#define B_WKT    ((ll)5242880)     // planes E=262144
#define B_W1AT   ((ll)6291456)     // planes E=262144
#define B_WKWT   ((ll)7340032)     // planes E=262144
#define B_WSCT   ((ll)8388608)     // planes E=524288 (rows512, K1024)
#define B_WPT    ((ll)10485760)    // planes E=262144
#define B_WCQT   ((ll)11534336)    // planes E=524288
#define B_WMT    ((ll)13631488)    // planes E=262144
#define B_WC1CT  ((ll)14680064)    // planes E=262144
#define B_NMBT   ((ll)15728640)    // planes E=524288 (rows512, K1024)
#define B_W1BT   ((ll)17825792)    // planes E=262144
#define B_QR     ((ll)18874368)    // planes E=262144 (question, K1024)
#define B_C0R    ((ll)19922944)    // planes E=131072
#define B_M0R    ((ll)20447232)    // planes E=131072
#define B_WC2R   ((ll)20971520)    // planes E=262144
#define B_KNOWT  ((ll)22020096)    // planes E=25690112
#define B_SPK    ((ll)124780544)   // planes E=25690112
#define B_WKP    ((ll)227540992)   // planes E=262144 (Wk original orientation)
#define B_QF     ((ll)228589568)   // fp32 131072 (q split-K accum)
#define B_TOTAL  ((ll)229113856)

__device__ __align__(1024) char g_s[B_TOTAL];

// ===================== arch-generic PTX helpers (sm_80/90 core) ============
__device__ __forceinline__ uint32_t smem_u32(const void* p) {
    uint32_t a;
    asm("{ .reg .u64 t; cvta.to.shared.u64 t, %1; cvt.u32.u64 %0, t; }"
        : "=r"(a) : "l"(p));
    return a;
}

#define MBARRIER_INIT(addr, cnt) \
    asm volatile("mbarrier.init.shared.b64 [%0], %1;" :: "r"(addr), "r"(cnt) : "memory")
#define MBARRIER_ARRIVE(addr) \
    asm volatile("mbarrier.arrive.shared.b64 _, [%0];" :: "r"(addr) : "memory")
#define MBARRIER_EXPECT_TX(addr, bytes) \
    asm volatile("mbarrier.arrive.expect_tx.shared.b64 _, [%0], %1;" \
                 :: "r"(addr), "r"(bytes) : "memory")
#define MBARRIER_WAIT_PARITY(addr, par) do { \
    uint32_t _m = (addr), _p = (par), _d; \
    asm volatile("{ .reg .pred p; mbarrier.try_wait.parity.acquire.cta.shared::cta.b64 p, [%1], %2;" \
                 " selp.b32 %0,1,0,p; }" : "=r"(_d) : "r"(_m), "r"(_p) : "memory"); \
    if (!_d) { \
        asm volatile("{ .reg .pred P1; WL_%=:" \
                     " mbarrier.try_wait.parity.acquire.cta.shared::cta.b64 P1, [%0], %1, 0x989680;" \
                     " @P1 bra.uni WD_%=; bra.uni WL_%=; WD_%=: }" \
                     :: "r"(_m), "r"(_p) : "memory"); \
    } \
} while (0)
#define FENCE_ASYNC() asm volatile("fence.proxy.async.shared::cta;" ::: "memory")

#define BULK_G2S(dst, src, bytes, mbar) \
    asm volatile("cp.async.bulk.shared::cluster.global.mbarrier::complete_tx::bytes " \
                 "[%0], [%1], %2, [%3];" \
                 :: "r"(dst), "l"(src), "r"(bytes), "r"(mbar) : "memory")

#define LDSM_X4(r0, r1, r2, r3, a) \
    asm volatile("ldmatrix.sync.aligned.m8n8.x4.shared.b16 {%0,%1,%2,%3}, [%4];" \
        : "=r"(r0), "=r"(r1), "=r"(r2), "=r"(r3) : "r"(a))

#define MMA16(d, a, b) \
    asm volatile("mma.sync.aligned.m16n8k16.row.col.f32.f16.f16.f32 " \
        "{%0,%1,%2,%3}, {%4,%5,%6,%7}, {%8,%9}, {%0,%1,%2,%3};" \
        : "+f"((d)[0]), "+f"((d)[1]), "+f"((d)[2]), "+f"((d)[3]) \
        : "r"((a)[0]), "r"((a)[1]), "r"((a)[2]), "r"((a)[3]), \
          "r"((b)[0]), "r"((b)[1]))

// element offset (in halves) inside a tiled-swizzled plane with kc chunks
__device__ __forceinline__ ll toff(int row, int k, int kc) {
    int r = row & 127;
    int quad = ((k >> 3) & 3) ^ ((r >> 1) & 3);
    return ((ll)((row >> 7) * kc + (k >> 5)) * 128 + r) * 32 + quad * 8 + (k & 7);
}

__device__ __forceinline__ void splitw_t(__half* hp, __half* lp, int row, int k,
                                         int kc, float v) {
    ll i = toff(row, k, kc);
    __half h = __float2half_rn(v);
    hp[i] = h;
    lp[i] = __float2half_rn(v - __half2float(h));
}
__device__ __forceinline__ void splitw2_t(__half* hp, __half* lp, int row, int k,
                                          int kc, float v0, float v1) {
    ll i = toff(row, k, kc);
    __half h0 = __float2half_rn(v0), h1 = __float2half_rn(v1);
    *(__half2*)(hp + i) = __halves2half2(h0, h1);
    *(__half2*)(lp + i) = __halves2half2(
        __float2half_rn(v0 - __half2float(h0)),
        __float2half_rn(v1 - __half2float(h1)));
}
// 8 consecutive k values (k 8-aligned) -> one 16B store per plane
__device__ __forceinline__ void splitw8_t(__half* hp, __half* lp, int row, int k,
                                          int kc, const float* f) {
    ll i = toff(row, k, kc);
    uint32_t hw[4], lw[4];
#pragma unroll
    for (int j = 0; j < 4; j++) {
        __half a = __float2half_rn(f[2*j]), b = __float2half_rn(f[2*j+1]);
        __half2 hh = __halves2half2(a, b);
        hw[j] = *(uint32_t*)&hh;
        __half2 l2 = __halves2half2(
            __float2half_rn(f[2*j]   - __half2float(a)),
            __float2half_rn(f[2*j+1] - __half2float(b)));
        lw[j] = *(uint32_t*)&l2;
    }
    *(uint4*)(hp + i) = make_uint4(hw[0], hw[1], hw[2], hw[3]);
    *(uint4*)(lp + i) = make_uint4(lw[0], lw[1], lw[2], lw[3]);
}

struct Op { const __half* h; const __half* l; int kc; };

#define SMB 131712

// ===================== heavy GEMM (MODE1 / MODE2) ==========================
template<int MODE>
__global__ __launch_bounds__(512, 1)
void tc_gemm(Op A1, Op A2, Op B1, Op B2, int K,
             __half* __restrict__ Ch, __half* __restrict__ Cl,
             int okc, const float* __restrict__ bias,
             const float* __restrict__ aux, const float* __restrict__ uv,
             float* __restrict__ logit)
{
    extern __shared__ char smem[];
    const uint32_t su = smem_u32(smem);
    const int tid = threadIdx.x;
    const int lane = tid & 31, wid = tid >> 5;
    const int wm = wid & 3, wn = wid >> 2;
    const int m0 = blockIdx.y * 128, n0 = blockIdx.x * 128;
    const int NC = K >> 5;
    const uint32_t mbF = su + 131072u, mbE = su + 131104u;

    if (tid == 0) {
#pragma unroll
        for (int s = 0; s < 4; s++) {
            MBARRIER_INIT(mbF + s * 8, 1);
            MBARRIER_INIT(mbE + s * 8, 16);
        }
        FENCE_ASYNC();
    }
    __syncthreads();

    auto issue = [&](int cn) {
        const bool a1 = cn < A1.kc, b1 = cn < B1.kc;
        const __half* ah = a1 ? A1.h : A2.h;
        const __half* al = a1 ? A1.l : A2.l;
        const __half* bh = b1 ? B1.h : B2.h;
        const __half* bl = b1 ? B1.l : B2.l;
        const int ca = a1 ? cn : cn - A1.kc;
        const int cb = b1 ? cn : cn - B1.kc;
        const int kca = a1 ? A1.kc : A2.kc;
        const int kcb = b1 ? B1.kc : B2.kc;
        const ll ao = ((ll)((m0 >> 7) * kca + ca)) * 8192;
        const ll bo = ((ll)((n0 >> 7) * kcb + cb)) * 8192;
        const uint32_t st = su + (uint32_t)(cn & 3) * 32768u;
        const uint32_t mb = mbF + (cn & 3) * 8;
        MBARRIER_EXPECT_TX(mb, 32768u);
        BULK_G2S(st,           (const char*)ah + ao, 8192u, mb);
        BULK_G2S(st + 8192u,   (const char*)al + ao, 8192u, mb);
        BULK_G2S(st + 16384u,  (const char*)bh + bo, 8192u, mb);
        BULK_G2S(st + 24576u,  (const char*)bl + bo, 8192u, mb);
    };

    if (tid == 0) { issue(0); if (NC > 1) issue(1); if (NC > 2) issue(2); }

    int ba[2], sa2[2], bb[2], sb2[2];
#pragma unroll
    for (int tm = 0; tm < 2; tm++) {
        int r = wm * 32 + tm * 16 + (lane & 7) + ((lane >> 3) & 1) * 8;
        ba[tm] = r * 64; sa2[tm] = (r >> 1) & 3;
    }
#pragma unroll
    for (int tp = 0; tp < 2; tp++) {
        int r = wn * 32 + tp * 16 + (lane & 7) + (lane >> 4) * 8;
        bb[tp] = r * 64; sb2[tp] = (r >> 1) & 3;
    }
    const int qa = lane >> 4, qb = (lane >> 3) & 1;

    float acc[2][4][4];
#pragma unroll
    for (int i = 0; i < 2; i++)
#pragma unroll
        for (int j = 0; j < 4; j++)
#pragma unroll
            for (int r = 0; r < 4; r++) acc[i][j][r] = 0.f;

    for (int c = 0; c < NC; c++) {
        if (tid == 0 && c + 3 < NC) {
            const int cn = c + 3;
            if (cn >= 4)
                MBARRIER_WAIT_PARITY(mbE + (cn & 3) * 8, ((cn >> 2) - 1) & 1);
            issue(cn);
        }
        MBARRIER_WAIT_PARITY(mbF + (c & 3) * 8, (c >> 2) & 1);
        const uint32_t st = su + (uint32_t)(c & 3) * 32768u;
#pragma unroll
        for (int kk2 = 0; kk2 < 2; kk2++) {
            uint32_t ah[2][4], al[2][4], bh[4][2], bl[4][2];
#pragma unroll
            for (int tm = 0; tm < 2; tm++) {
                const uint32_t ad = st + ba[tm]
                    + (uint32_t)((((qa + kk2 * 2) ^ sa2[tm]) & 3) * 16);
                LDSM_X4(ah[tm][0], ah[tm][1], ah[tm][2], ah[tm][3], ad);
                LDSM_X4(al[tm][0], al[tm][1], al[tm][2], al[tm][3], ad + 8192u);
            }
#pragma unroll
            for (int tp = 0; tp < 2; tp++) {
                const uint32_t bd = st + 16384u + bb[tp]
                    + (uint32_t)((((qb + kk2 * 2) ^ sb2[tp]) & 3) * 16);
                uint32_t r0, r1, r2, r3;
                LDSM_X4(r0, r1, r2, r3, bd);
                bh[2*tp][0] = r0; bh[2*tp][1] = r1;
                bh[2*tp+1][0] = r2; bh[2*tp+1][1] = r3;
                LDSM_X4(r0, r1, r2, r3, bd + 8192u);
                bl[2*tp][0] = r0; bl[2*tp][1] = r1;
                bl[2*tp+1][0] = r2; bl[2*tp+1][1] = r3;
            }
#pragma unroll
            for (int tm = 0; tm < 2; tm++)
#pragma unroll
                for (int tn = 0; tn < 4; tn++) {
                    MMA16(acc[tm][tn], ah[tm], bh[tn]);
                    MMA16(acc[tm][tn], ah[tm], bl[tn]);
                    MMA16(acc[tm][tn], al[tm], bh[tn]);
                }
        }
        if (lane == 0) MBARRIER_ARRIVE(mbE + (c & 3) * 8);
    }

    float* rowsum = (float*)(smem + 131136);
    if (MODE == 2) {
        __syncthreads();
        if (tid < 128) rowsum[tid] = 0.f;
        __syncthreads();
    }

#pragma unroll
    for (int tm = 0; tm < 2; tm++) {
        const int lr0 = wm * 32 + tm * 16 + (lane >> 2);
        const int r0 = m0 + lr0, r1 = r0 + 8;
        if (MODE == 1) {
            const int b0 = r0 / NHW, b1 = r1 / NHW;
#pragma unroll
            for (int tn = 0; tn < 4; tn++) {
                const int gn = n0 + wn * 32 + tn * 8 + (lane & 3) * 2;
                const float bb0 = bias[gn], bb1 = bias[gn + 1];
                const float* a0 = aux + (ll)b0 * 512 + gn;
                const float* a1 = aux + (ll)b1 * 512 + gn;
                splitw2_t(Ch, Cl, r0, gn, okc,
                          (acc[tm][tn][0] + bb0) * a0[0],
                          (acc[tm][tn][1] + bb1) * a0[1]);
                splitw2_t(Ch, Cl, r1, gn, okc,
                          (acc[tm][tn][2] + bb0) * a1[0],
                          (acc[tm][tn][3] + bb1) * a1[1]);
            }
        } else {
            const int b0 = r0 / NHW, b1 = r1 / NHW;
            float p0 = 0.f, p1 = 0.f;
#pragma unroll
            for (int tn = 0; tn < 4; tn++) {
                const int gn = n0 + wn * 32 + tn * 8 + (lane & 3) * 2;
                const float* x0 = aux + (ll)b0 * 512 + gn;
                const float* u0 = uv  + (ll)b0 * 512 + gn;
                const float* x1 = aux + (ll)b1 * 512 + gn;
                const float* u1 = uv  + (ll)b1 * 512 + gn;
                p0 += fmaxf(acc[tm][tn][0] + x0[0], 0.f) * u0[0]
                    + fmaxf(acc[tm][tn][1] + x0[1], 0.f) * u0[1];
                p1 += fmaxf(acc[tm][tn][2] + x1[0], 0.f) * u1[0]
                    + fmaxf(acc[tm][tn][3] + x1[1], 0.f) * u1[1];
            }
            p0 += __shfl_xor_sync(0xffffffffu, p0, 1);
            p0 += __shfl_xor_sync(0xffffffffu, p0, 2);
            p1 += __shfl_xor_sync(0xffffffffu, p1, 1);
            p1 += __shfl_xor_sync(0xffffffffu, p1, 2);
            if ((lane & 3) == 0) {
                atomicAdd(&rowsum[lr0], p0);
                atomicAdd(&rowsum[lr0 + 8], p1);
            }
        }
    }
    if (MODE == 2) {
        __syncthreads();
        if (tid < 128) atomicAdd(&logit[m0 + tid], rowsum[tid]);
    }
}

// ============ batched small GEMM (desc per blockIdx.z) =====================
struct GD {
    const __half *ah, *al; int akc;
    const __half *bh, *bl; int bkc;
    int K;
    float* C; __half* Ch; __half* Cl; int okc;
    const float* bias; int act; int atomic; int my;
};
struct GDBatch { GD d[4]; };

__global__ __launch_bounds__(512, 1)
void tc_gemmb(GDBatch tb)
{
    const GD g = tb.d[blockIdx.z];
    if (blockIdx.y >= g.my) return;
    extern __shared__ char smem[];
    const uint32_t su = smem_u32(smem);
    const int tid = threadIdx.x;
    const int lane = tid & 31, wid = tid >> 5;
    const int wm = wid & 3, wn = wid >> 2;
    const int m0 = blockIdx.y * 128, n0 = blockIdx.x * 128;
    const int NC = g.K >> 5;
    const uint32_t mbF = su + 131072u, mbE = su + 131104u;

    if (tid == 0) {
#pragma unroll
        for (int s = 0; s < 4; s++) {
            MBARRIER_INIT(mbF + s * 8, 1);
            MBARRIER_INIT(mbE + s * 8, 16);
        }
        FENCE_ASYNC();
    }
    __syncthreads();

    auto issue = [&](int cn) {
        const ll ao = ((ll)((m0 >> 7) * g.akc + cn)) * 8192;
        const ll bo = ((ll)((n0 >> 7) * g.bkc + cn)) * 8192;
        const uint32_t st = su + (uint32_t)(cn & 3) * 32768u;
        const uint32_t mb = mbF + (cn & 3) * 8;
        MBARRIER_EXPECT_TX(mb, 32768u);
        BULK_G2S(st,           (const char*)g.ah + ao, 8192u, mb);
        BULK_G2S(st + 8192u,   (const char*)g.al + ao, 8192u, mb);
        BULK_G2S(st + 16384u,  (const char*)g.bh + bo, 8192u, mb);
        BULK_G2S(st + 24576u,  (const char*)g.bl + bo, 8192u, mb);
    };

    if (tid == 0) { issue(0); if (NC > 1) issue(1); if (NC > 2) issue(2); }

    int ba[2], sa2[2], bb[2], sb2[2];
#pragma unroll
    for (int tm = 0; tm < 2; tm++) {
        int r = wm * 32 + tm * 16 + (lane & 7) + ((lane >> 3) & 1) * 8;
        ba[tm] = r * 64; sa2[tm] = (r >> 1) & 3;
    }
#pragma unroll
    for (int tp = 0; tp < 2; tp++) {
        int r = wn * 32 + tp * 16 + (lane & 7) + (lane >> 4) * 8;
        bb[tp] = r * 64; sb2[tp] = (r >> 1) & 3;
    }
    const int qa = lane >> 4, qb = (lane >> 3) & 1;

    float acc[2][4][4];
#pragma unroll
    for (int i = 0; i < 2; i++)
#pragma unroll
        for (int j = 0; j < 4; j++)
#pragma unroll
            for (int r = 0; r < 4; r++) acc[i][j][r] = 0.f;

    for (int c = 0; c < NC; c++) {
        if (tid == 0 && c + 3 < NC) {
            const int cn = c + 3;
            if (cn >= 4)
                MBARRIER_WAIT_PARITY(mbE + (cn & 3) * 8, ((cn >> 2) - 1) & 1);
            issue(cn);
        }
        MBARRIER_WAIT_PARITY(mbF + (c & 3) * 8, (c >> 2) & 1);
        const uint32_t st = su + (uint32_t)(c & 3) * 32768u;
#pragma unroll
        for (int kk2 = 0; kk2 < 2; kk2++) {
            uint32_t ah[2][4], al[2][4], bh[4][2], bl[4][2];
#pragma unroll
            for (int tm = 0; tm < 2; tm++) {
                const uint32_t ad = st + ba[tm]
                    + (uint32_t)((((qa + kk2 * 2) ^ sa2[tm]) & 3) * 16);
                LDSM_X4(ah[tm][0], ah[tm][1], ah[tm][2], ah[tm][3], ad);
                LDSM_X4(al[tm][0], al[tm][1], al[tm][2], al[tm][3], ad + 8192u);
            }
#pragma unroll
            for (int tp = 0; tp < 2; tp++) {
                const uint32_t bd = st + 16384u + bb[tp]
                    + (uint32_t)((((qb + kk2 * 2) ^ sb2[tp]) & 3) * 16);
                uint32_t r0, r1, r2, r3;
                LDSM_X4(r0, r1, r2, r3, bd);
                bh[2*tp][0] = r0; bh[2*tp][1] = r1;
                bh[2*tp+1][0] = r2; bh[2*tp+1][1] = r3;
                LDSM_X4(r0, r1, r2, r3, bd + 8192u);
                bl[2*tp][0] = r0; bl[2*tp][1] = r1;
                bl[2*tp+1][0] = r2; bl[2*tp+1][1] = r3;
            }
#pragma unroll
            for (int tm = 0; tm < 2; tm++)
#pragma unroll
                for (int tn = 0; tn < 4; tn++) {
                    MMA16(acc[tm][tn], ah[tm], bh[tn]);
                    MMA16(acc[tm][tn], ah[tm], bl[tn]);
                    MMA16(acc[tm][tn], al[tm], bh[tn]);
                }
        }
        if (lane == 0) MBARRIER_ARRIVE(mbE + (c & 3) * 8);
    }

#pragma unroll
    for (int tm = 0; tm < 2; tm++) {
        const int lr0 = wm * 32 + tm * 16 + (lane >> 2);
        const int r0 = m0 + lr0, r1 = r0 + 8;
#pragma unroll
        for (int tn = 0; tn < 4; tn++) {
            const int gn = n0 + wn * 32 + tn * 8 + (lane & 3) * 2;
            float v0 = acc[tm][tn][0], v1 = acc[tm][tn][1];
            float v2 = acc[tm][tn][2], v3 = acc[tm][tn][3];
            if (g.bias) {
                float b0 = g.bias[gn], b1 = g.bias[gn + 1];
                v0 += b0; v1 += b1; v2 += b0; v3 += b1;
            }
            if (g.act == 1) {
                v0 = tanhf(v0); v1 = tanhf(v1);
                v2 = tanhf(v2); v3 = tanhf(v3);
            }
            if (g.atomic) {
                atomicAdd(&g.C[(ll)r0 * 512 + gn], v0);
                atomicAdd(&g.C[(ll)r0 * 512 + gn + 1], v1);
                atomicAdd(&g.C[(ll)r1 * 512 + gn], v2);
                atomicAdd(&g.C[(ll)r1 * 512 + gn + 1], v3);
            } else {
                if (g.C) {
                    *(float2*)&g.C[(ll)r0 * 512 + gn] = make_float2(v0, v1);
                    *(float2*)&g.C[(ll)r1 * 512 + gn] = make_float2(v2, v3);
                }
                if (g.Ch) {
                    splitw2_t(g.Ch, g.Cl, r0, gn, g.okc, v0, v1);
                    splitw2_t(g.Ch, g.Cl, r1, gn, g.okc, v2, v3);
                }
            }
        }
    }
}

// ===================== vectorized transposes & split producers =============
// knowT: grid (7, 8, 256), block (32,8); 32 n x 64 d per block, 16B stores.
__global__ __launch_bounds__(256)
void transpose_k(const float* __restrict__ know, __half* __restrict__ kh,
                 __half* __restrict__ kl)
{
    __shared__ float t[32][65];
    const int b = blockIdx.z;
    const int n0 = blockIdx.x * 32, d0 = blockIdx.y * 64;
    const int tx = threadIdx.x, ty = threadIdx.y;
#pragma unroll
    for (int r = 0; r < 8; r++) {
        int dl = ty + r * 8;
        int n = n0 + tx;
        t[tx][dl] = (n < NHW) ? know[((ll)b * ND + d0 + dl) * NHW + n] : 0.f;
    }
    __syncthreads();
    const int tid = ty * 32 + tx;
    const int nl = tid & 31, dg = tid >> 5;
    if (n0 + nl < NHW) {
        float f[8];
#pragma unroll
        for (int i = 0; i < 8; i++) f[i] = t[nl][dg * 8 + i];
        splitw8_t(kh, kl, b * NHW + n0 + nl, d0 + dg * 8, 16, f);
    }
}

struct TDesc { const float* src; __half* dh; ll E; int R; int kc; };
struct TBatch { TDesc d[9]; };

// dst tiled plane [n, k] = src[k, n]; grid (16, 16, 9), block (32,8);
// 32 n x 64 k per block, 16B stores.
__global__ __launch_bounds__(256)
void trans_w(TBatch tb)
{
    const TDesc td = tb.d[blockIdx.z];
    const int k0 = blockIdx.y * 64, n0 = blockIdx.x * 32;
    if (k0 >= td.R) return;
    __half* dl = td.dh + td.E;
    __shared__ float t[32][65];
    const int tx = threadIdx.x, ty = threadIdx.y;
#pragma unroll
    for (int r = 0; r < 8; r++) {
        int kk = ty + r * 8;
        t[tx][kk] = td.src[(ll)(k0 + kk) * 512 + n0 + tx];
    }
    __syncthreads();
    const int tid = ty * 32 + tx;
    const int nl = tid & 31, kg = tid >> 5;
    float f[8];
#pragma unroll
    for (int i = 0; i < 8; i++) f[i] = t[nl][kg * 8 + i];
    splitw8_t(td.dh, dl, n0 + nl, k0 + kg * 8, td.kc, f);
}

// nmBT chunks 16-31: 16B stores; grid 128, block 256
__global__ void wsumT_kernel(const float* __restrict__ Wwcat,
                             __half* __restrict__ nh)
{
    int g = blockIdx.x * 256 + threadIdx.x;   // 32768 groups
    int n = g >> 6, k = (g & 63) * 8;
    float f[8];
#pragma unroll
    for (int i = 0; i < 8; i++)
        f[i] = Wwcat[(ll)(512 + k + i) * 512 + n] + Wwcat[(ll)(1024 + k + i) * 512 + n];
    splitw8_t(nh, nh + 524288, n, 512 + k, 32, f);
}

__global__ void b2init_kernel(const float* __restrict__ bc1, float* __restrict__ b2)
{
    int d = blockIdx.x * 256 + threadIdx.x;
    b2[d] = bc1[d];
}

__global__ void bias2_kernel(const float* __restrict__ Wc1, const float* __restrict__ bk,
                             float* __restrict__ b2)
{
    int d = blockIdx.x * 256 + threadIdx.x;
    int e0 = blockIdx.y * 32;
    float acc = 0.f;
#pragma unroll
    for (int e = 0; e < 32; e++)
        acc += bk[e0 + e] * Wc1[(ll)(512 + e0 + e) * 512 + d];
    atomicAdd(&b2[d], acc);
}

// zero split-K accumulators + logit; outM pre-filled with bwcat broadcast
__global__ void init_bufs(const float* __restrict__ bwcat,
                          char* __restrict__ Sb, float* __restrict__ outM)
{
    int i = blockIdx.x * 256 + threadIdx.x;
    ((float*)(Sb + B_QF))[i] = 0.f;
    ((float*)(Sb + B_CQ))[i] = 0.f;
    if (i < NM) ((float*)(Sb + B_LOGIT))[i] = 0.f;
    outM[i] = bwcat[i & 511];
}

// q planes = split(tanh(qf + bsc)) — vectorized 8-wide
__global__ void tanhsplit_kernel(const float* __restrict__ qf,
                                 const float* __restrict__ bsc,
                                 __half* __restrict__ qh)
{
    int g = blockIdx.x * 256 + threadIdx.x;   // 16384 groups
    int row = g >> 6, k = (g & 63) * 8;
    float f[8];
#pragma unroll
    for (int i = 0; i < 8; i++)
        f[i] = tanhf(qf[(ll)row * 512 + k + i] + bsc[k + i]);
    splitw8_t(qh, qh + 131072, row, k, 16, f);
}

// vectorized split copies (8 consecutive k per thread)
__global__ void copy_split(const float* __restrict__ q, const float* __restrict__ c0,
                           const float* __restrict__ m0, const float* __restrict__ wc2,
                           const float* __restrict__ wk,
                           char* __restrict__ Sb)
{
    int g = blockIdx.x * 256 + threadIdx.x;   // 131072 groups
    const float* src; __half* h; ll E; int ld, kc, j;
    if (g < 32768)       { src = q;   h = (__half*)(Sb + B_QR);   E = 262144; ld = 1024; kc = 32; j = g; }
    else if (g < 49152)  { src = c0;  h = (__half*)(Sb + B_C0R);  E = 131072; ld = 512;  kc = 16; j = g - 32768; }
    else if (g < 65536)  { src = m0;  h = (__half*)(Sb + B_M0R);  E = 131072; ld = 512;  kc = 16; j = g - 49152; }
    else if (g < 98304)  { src = wc2; h = (__half*)(Sb + B_WC2R); E = 262144; ld = 512;  kc = 16; j = g - 65536; }
    else                 { src = wk;  h = (__half*)(Sb + B_WKP);  E = 262144; ld = 512;  kc = 16; j = g - 98304; }
    const int gpr = ld >> 3;
    int row = j / gpr, k = (j % gpr) * 8;
    float f[8];
    const float* s = src + (ll)row * ld + k;
#pragma unroll
    for (int i = 0; i < 8; i++) f[i] = s[i];
    splitw8_t(h, h + E, row, k, kc, f);
}

// ===================== attention / reductions ==============================
__global__ __launch_bounds__(256)
void attnc_kernel(const float* __restrict__ words, const float* __restrict__ cq,
                  const float* __restrict__ bcq,
                  const float* __restrict__ wac, const float* __restrict__ bac,
                  float* __restrict__ control)
{
    const int b = blockIdx.x, tid = threadIdx.x;
    const int warp = tid >> 5, lane = tid & 31;
    __shared__ float cw[ND];
    __shared__ float sa[NS];
    for (int d = tid; d < ND; d += 256)
        cw[d] = (cq[(ll)b * ND + d] + bcq[d]) * wac[d];
    __syncthreads();
#pragma unroll
    for (int r = 0; r < 4; r++) {
        int s = warp * 4 + r;
        const float* wp = words + ((ll)b * NS + s) * ND;
        float acc = 0.f;
        for (int d = lane; d < ND; d += 32) acc += cw[d] * wp[d];
#pragma unroll
        for (int o = 16; o; o >>= 1) acc += __shfl_xor_sync(0xffffffffu, acc, o);
        if (lane == 0) sa[s] = acc + bac[0];
    }
    __syncthreads();
    if (warp == 0) {
        float v = sa[lane], mx = v;
#pragma unroll
        for (int o = 16; o; o >>= 1) mx = fmaxf(mx, __shfl_xor_sync(0xffffffffu, mx, o));
        float e = expf(v - mx), sm = e;
#pragma unroll
        for (int o = 16; o; o >>= 1) sm += __shfl_xor_sync(0xffffffffu, sm, o);
        sa[lane] = e / sm;
    }
    __syncthreads();
    for (int d = tid; d < ND; d += 256) {
        float acc = 0.f;
#pragma unroll 8
        for (int s = 0; s < NS; s++) acc += sa[s] * words[((ll)b * NS + s) * ND + d];
        control[(ll)b * ND + d] = acc;
    }
}

// v = control*war -> split planes (c_b dropped: softmax-shift-invariant)
__global__ void vsplit_kernel(const float* __restrict__ control,
                              const float* __restrict__ war,
                              __half* __restrict__ vh)
{
    int g = blockIdx.x * 256 + threadIdx.x;   // 16384 groups
    int b = g >> 6, k = (g & 63) * 8;
    float f[8];
#pragma unroll
    for (int i = 0; i < 8; i++)
        f[i] = control[(ll)b * 512 + k + i] * war[k + i];
    splitw8_t(vh, vh + 131072, b, k, 16, f);
}

__global__ __launch_bounds__(256)
void softmaxn_kernel(const float* __restrict__ logit, float* __restrict__ ar)
{
    const int b = blockIdx.x, tid = threadIdx.x;
    __shared__ float s[256];
    float v = (tid < NHW) ? logit[(ll)b * NHW + tid] : -1e30f;
    s[tid] = v; __syncthreads();
    for (int o = 128; o; o >>= 1) { if (tid < o) s[tid] = fmaxf(s[tid], s[tid + o]); __syncthreads(); }
    float mx = s[0]; __syncthreads();
    float e = (tid < NHW) ? expf(v - mx) : 0.f;
    s[tid] = e; __syncthreads();
    for (int o = 128; o; o >>= 1) { if (tid < o) s[tid] += s[tid + o]; __syncthreads(); }
    float sum = s[0];
    if (tid < NHW) ar[(ll)b * NHW + tid] = e / sum;
}

__global__ __launch_bounds__(256)
void read_kernel(const float* __restrict__ know, const float* __restrict__ ar,
                 __half* __restrict__ rh)
{
    const int b = blockIdx.x, tid = threadIdx.x;
    const int warp = tid >> 5, lane = tid & 31;
    __shared__ float s[NHW];
    if (tid < NHW) s[tid] = ar[(ll)b * NHW + tid];
    __syncthreads();
    for (int d = warp; d < ND; d += 8) {
        const float* kp = know + ((ll)b * ND + d) * NHW;
        float acc = 0.f;
        for (int n = lane; n < NHW; n += 32) acc += kp[n] * s[n];
#pragma unroll
        for (int o = 16; o; o >>= 1) acc += __shfl_xor_sync(0xffffffffu, acc, o);
        if (lane == 0) splitw_t(rh, rh + 131072, b, d, 16, acc);
    }
}

// ===========================================================================
extern "C" void kernel_launch(void* const* d_in, const int* in_sizes, int n_in,
                              void* d_out, int out_size)
{
    const float* words    = (const float*)d_in[0];
    const float* question = (const float*)d_in[1];
    const float* know     = (const float*)d_in[2];
    const float* control0 = (const float*)d_in[3];
    const float* memory0  = (const float*)d_in[4];
    const float* Wsc  = (const float*)d_in[5];
    const float* bsc  = (const float*)d_in[6];
    const float* Wp   = (const float*)d_in[7];
    const float* bp   = (const float*)d_in[8];
    const float* Wcq  = (const float*)d_in[9];
    const float* bcq  = (const float*)d_in[10];
    const float* wac  = (const float*)d_in[11];
    const float* bac  = (const float*)d_in[12];
    const float* Wm   = (const float*)d_in[13];
    const float* bm   = (const float*)d_in[14];
    const float* Wk   = (const float*)d_in[15];
    const float* bk   = (const float*)d_in[16];
    const float* Wc1  = (const float*)d_in[17];
    const float* bc1  = (const float*)d_in[18];
    const float* Wc2  = (const float*)d_in[19];
    // bc2/bar (d_in[20], d_in[22]) dead: per-batch constant in logit_r ->
    // softmax-shift-invariant. d_in[23..26] dead: softmax over length-1 axis.
    const float* war  = (const float*)d_in[21];
    const float* Wwcat = (const float*)d_in[27];
    const float* bwcat = (const float*)d_in[28];

    cudaFuncSetAttribute(tc_gemm<1>, cudaFuncAttributeMaxDynamicSharedMemorySize, SMB);
    cudaFuncSetAttribute(tc_gemm<2>, cudaFuncAttributeMaxDynamicSharedMemorySize, SMB);
    cudaFuncSetAttribute(tc_gemmb, cudaFuncAttributeMaxDynamicSharedMemorySize, SMB);

    char* Sb = nullptr;
    cudaGetSymbolAddress((void**)&Sb, g_s);

    float* outC = (float*)d_out;
    float* outM = (float*)d_out + (ll)NB * ND;

    auto F  = [&](ll off) { return (float*)(Sb + off); };
    auto Hh = [&](ll off) { return (__half*)(Sb + off); };
    auto OP = [&](ll off, ll E, int kc) -> Op {
        __half* h = (__half*)(Sb + off);
        return { h, h + E, kc };
    };
    Op Z = { nullptr, nullptr, 0 };

    // ---------- prep (independent, wide) ----------
    init_bufs<<<512, 256>>>(bwcat, Sb, outM);
    {
        TBatch tb;
        tb.d[0] = { Wk,                     Hh(B_WKT),   262144, 512, 16 };
        tb.d[1] = { Wc1,                    Hh(B_W1AT),  262144, 512, 16 };
        tb.d[2] = { Wc1 + (ll)ND * ND,      Hh(B_W1BT),  262144, 512, 16 };
        tb.d[3] = { Wsc,                    Hh(B_WSCT),  524288, 1024, 32 };
        tb.d[4] = { Wp,                     Hh(B_WPT),   262144, 512, 16 };
        tb.d[5] = { Wcq,                    Hh(B_WCQT),  524288, 1024, 32 };
        tb.d[6] = { Wm,                     Hh(B_WMT),   262144, 512, 16 };
        tb.d[7] = { Wc1 + (ll)2 * ND * ND,  Hh(B_WC1CT), 262144, 512, 16 };
        tb.d[8] = { Wwcat,                  Hh(B_NMBT),  524288, 512, 32 };
        trans_w<<<dim3(16, 16, 9), dim3(32, 8)>>>(tb);
    }
    transpose_k<<<dim3(7, 8, NB), dim3(32, 8)>>>(know, Hh(B_KNOWT),
                                                 Hh(B_KNOWT) + 25690112);
    wsumT_kernel<<<128, 256>>>(Wwcat, Hh(B_NMBT));
    b2init_kernel<<<2, 256>>>(bc1, F(B_BIAS2));
    bias2_kernel<<<dim3(2, 16), 256>>>(Wc1, bk, F(B_BIAS2));
    copy_split<<<512, 256>>>(question, control0, memory0, Wc2, Wk, Sb);

    const ll CH16 = 16 * 4096;   // +16 chunks (halves) within a K=1024 layout

    // ---------- batch1: q-half1, q-half2 (split-K atomic), pm, WkW1b ------
    {
        GDBatch b{};
        b.d[0] = { Hh(B_QR), Hh(B_QR) + 262144, 32,
                   Hh(B_WSCT), Hh(B_WSCT) + 524288, 32,
                   512, F(B_QF), nullptr, nullptr, 0, nullptr, 0, 1, 2 };
        b.d[1] = { Hh(B_QR) + CH16, Hh(B_QR) + 262144 + CH16, 32,
                   Hh(B_WSCT) + CH16, Hh(B_WSCT) + 524288 + CH16, 32,
                   512, F(B_QF), nullptr, nullptr, 0, nullptr, 0, 1, 2 };
        b.d[2] = { Hh(B_M0R), Hh(B_M0R) + 131072, 16,
                   Hh(B_WMT), Hh(B_WMT) + 262144, 16,
                   512, F(B_PMF), Hh(B_PMP), Hh(B_PMP) + 131072, 16, bm, 0, 0, 2 };
        b.d[3] = { Hh(B_W1BT), Hh(B_W1BT) + 262144, 16,
                   Hh(B_WKP), Hh(B_WKP) + 262144, 16,
                   512, nullptr, Hh(B_WKWT), Hh(B_WKWT) + 262144, 16,
                   nullptr, 0, 0, 4 };
        tc_gemmb<<<dim3(4, 4, 4), 512, SMB>>>(b);
    }
    tanhsplit_kernel<<<64, 256>>>(F(B_QF), bsc, Hh(B_Q));

    // ---------- HEAVY 1: spk = (knowT @ Wk + bk) * pm[b] -> planes --------
    tc_gemm<1><<<dim3(4, NM / 128), 512, SMB>>>(
        OP(B_KNOWT, 25690112, 16), Z, OP(B_WKT, 262144, 16), Z, 512,
        Hh(B_SPK), Hh(B_SPK) + 25690112, 16, bk,
        F(B_PMF), nullptr, nullptr);

    // ---------- batch2: pa, pmc ----------
    {
        GDBatch b{};
        b.d[0] = { Hh(B_Q), Hh(B_Q) + 131072, 16,
                   Hh(B_WPT), Hh(B_WPT) + 262144, 16,
                   512, nullptr, Hh(B_PA), Hh(B_PA) + 131072, 16, bp, 0, 0, 2 };
        b.d[1] = { Hh(B_PMP), Hh(B_PMP) + 131072, 16,
                   Hh(B_WC1CT), Hh(B_WC1CT) + 262144, 16,
                   512, F(B_PMC), nullptr, nullptr, 0, F(B_BIAS2), 0, 0, 2 };
        tc_gemmb<<<dim3(4, 2, 2), 512, SMB>>>(b);
    }
    // ---------- cq split-K batch (atomic into zeroed B_CQ) ----------
    {
        GDBatch b{};
        b.d[0] = { Hh(B_C0R), Hh(B_C0R) + 131072, 16,
                   Hh(B_WCQT), Hh(B_WCQT) + 524288, 32,
                   512, F(B_CQ), nullptr, nullptr, 0, nullptr, 0, 1, 2 };
        b.d[1] = { Hh(B_PA), Hh(B_PA) + 131072, 16,
                   Hh(B_WCQT) + CH16, Hh(B_WCQT) + 524288 + CH16, 32,
                   512, F(B_CQ), nullptr, nullptr, 0, nullptr, 0, 1, 2 };
        tc_gemmb<<<dim3(4, 2, 2), 512, SMB>>>(b);
    }
    attnc_kernel<<<NB, 256>>>(words, F(B_CQ), bcq, wac, bac, outC);
    vsplit_kernel<<<64, 256>>>(outC, war, Hh(B_V));
    // u = v @ Wc2
    {
        GDBatch b{};
        b.d[0] = { Hh(B_V), Hh(B_V) + 131072, 16,
                   Hh(B_WC2R), Hh(B_WC2R) + 262144, 16,
                   512, F(B_U), nullptr, nullptr, 0, nullptr, 0, 0, 2 };
        tc_gemmb<<<dim3(4, 2, 1), 512, SMB>>>(b);
    }
    // ---------- HEAVY 2 ----------
    tc_gemm<2><<<dim3(4, NM / 128), 512, SMB>>>(
        OP(B_SPK, 25690112, 16), OP(B_KNOWT, 25690112, 16),
        OP(B_W1AT, 262144, 16), OP(B_WKWT, 262144, 16), 1024,
        nullptr, nullptr, 16, nullptr,
        F(B_PMC), F(B_U), F(B_LOGIT));

    softmaxn_kernel<<<NB, 256>>>(F(B_LOGIT), F(B_AR));
    read_kernel<<<NB, 256>>>(know, F(B_AR), Hh(B_READ));

    // ---------- next_mem split-K batch (atomic into bwcat-filled outM) ----
    {
        GDBatch b{};
        b.d[0] = { Hh(B_READ), Hh(B_READ) + 131072, 16,
                   Hh(B_NMBT), Hh(B_NMBT) + 524288, 32,
                   512, outM, nullptr, nullptr, 0, nullptr, 0, 1, 2 };
        b.d[1] = { Hh(B_M0R), Hh(B_M0R) + 131072, 16,
                   Hh(B_NMBT) + CH16, Hh(B_NMBT) + 524288 + CH16, 32,
                   512, outM, nullptr, nullptr, 0, nullptr, 0, 1, 2 };
        tc_gemmb<<<dim3(4, 2, 2), 512, SMB>>>(b);
    }
}